// round 13
// baseline (speedup 1.0000x reference)
#include <cuda_runtime.h>
#include <cuda_bf16.h>
#include <math.h>
#include <stdint.h>

// ---------------- problem constants ----------------
#define NROWS 25000
#define NQ    8000
#define XD    100
#define YD    120
#define HID   100
#define NQPAD 8064          // 63*128
#define NTPAD 25088         // 196*128
#define QTILES 63
#define GSPLIT 14
#define NCH_PER 14
#define MP    132
#define WSTRIDE (128 * MP)

// ---------------- scratch ----------------
__device__ __align__(16) float g_xmap[NROWS * YD];
__device__ __align__(16) float g_ymap[NROWS * XD];
__device__ __align__(16) float g_xrt [NROWS * XD];
__device__ __align__(16) float g_yrt [NROWS * YD];
__device__ uint32_t g_Wt[4 * WSTRIDE];
__device__ __align__(16) char g_Qb8A[NQPAD * 128];
__device__ __align__(16) char g_Qb8B[NQPAD * 128];
__device__ __align__(16) char g_Tb8A[NTPAD * 128];
__device__ __align__(16) char g_Tb8B[NTPAD * 128];
__device__ __align__(8) float2 g_metaA[NTPAD];   // (tn, 2*st_row)
__device__ __align__(8) float2 g_metaB[NTPAD];
__device__ unsigned g_sqbits[2];                 // max|q| bits per side
__device__ unsigned g_mbA[NQ];
__device__ unsigned g_mbB[NQ];

// ---------------- helpers ----------------
__device__ __forceinline__ uint32_t smem_u32(const void* p) {
    uint32_t a;
    asm("{ .reg .u64 t; cvta.to.shared.u64 t, %1; cvt.u32.u64 %0, t; }" : "=r"(a) : "l"(p));
    return a;
}
__device__ __forceinline__ void cpa16(uint32_t dst, const void* src) {
    asm volatile("cp.async.cg.shared.global [%0], [%1], 16;" :: "r"(dst), "l"(src));
}
#define CP_COMMIT() asm volatile("cp.async.commit_group;" ::: "memory")
#define CP_WAIT0()  asm volatile("cp.async.wait_group 0;" ::: "memory")

__device__ __forceinline__ uint32_t f2tf32(float v) {
    uint32_t r;
    asm("cvt.rna.tf32.f32 %0, %1;" : "=r"(r) : "f"(v));
    return r;
}
// monotone float -> sortable unsigned
__device__ __forceinline__ unsigned enc(float f) {
    unsigned b = __float_as_uint(f);
    return b ^ ((unsigned)(((int)b) >> 31) | 0x80000000u);
}
__device__ __forceinline__ char q8(float v, float inv) {
    int x = __float2int_rn(v * inv);
    return (char)max(-127, min(127, x));
}

// ---------------- init ----------------
__global__ void k_init(float* out) {
    int i = blockIdx.x * 256 + threadIdx.x;
    if (i == 0) { out[0] = 0.0f; g_sqbits[0] = 0u; g_sqbits[1] = 0u; }
    if (i < NQ) { g_mbA[i] = 0xFFFFFFFFu; g_mbB[i] = 0xFFFFFFFFu; }
}

// ---------------- weight prep (transposed, tf32 RNA, pitch MP) --------------
__global__ void k_wprep(const float* __restrict__ w0, const float* __restrict__ w1,
                        const float* __restrict__ w2, const float* __restrict__ w3)
{
    int idx = blockIdx.x * 256 + threadIdx.x;
    if (idx >= 4 * WSTRIDE) return;
    int m = idx / WSTRIDE, r = idx - m * WSTRIDE;
    int n = r / MP, k = r - n * MP;
    const float* src; int Kd, Nd;
    if (m == 0)      { src = w0; Kd = XD;  Nd = HID; }
    else if (m == 1) { src = w1; Kd = HID; Nd = YD;  }
    else if (m == 2) { src = w2; Kd = YD;  Nd = HID; }
    else             { src = w3; Kd = HID; Nd = XD;  }
    float v = (n < Nd && k < Kd) ? src[k * Nd + n] : 0.0f;
    g_Wt[idx] = f2tf32(v);
}

// ---------------- target prep: int8 quantize + (tn, 2*st) meta --------------
__global__ void k_prep_t8(const float* __restrict__ x_w, const float* __restrict__ y_w)
{
    int z = blockIdx.y;
    const float* T = z ? x_w : y_w;
    int K = z ? XD : YD;
    char4* Tb = (char4*)(z ? g_Tb8B : g_Tb8A);
    float2* meta = z ? g_metaB : g_metaA;
    int wid = threadIdx.x >> 5, lane = threadIdx.x & 31;
    int row = blockIdx.x * 8 + wid;
    if (row >= NTPAD) return;
    float4 v = make_float4(0.f, 0.f, 0.f, 0.f);
    if (row < NROWS) {
        int c = lane * 4;
        if (c < K) v = *(const float4*)(T + (size_t)row * K + c);
    }
    float s = v.x * v.x + v.y * v.y + v.z * v.z + v.w * v.w;
    float mx = fmaxf(fmaxf(fabsf(v.x), fabsf(v.y)), fmaxf(fabsf(v.z), fabsf(v.w)));
#pragma unroll
    for (int o = 16; o; o >>= 1) {
        s  += __shfl_xor_sync(0xffffffffu, s, o);
        mx  = fmaxf(mx, __shfl_xor_sync(0xffffffffu, mx, o));
    }
    float mxs = fmaxf(mx, 1e-20f);
    float inv = 127.0f / mxs;
    char4 q;
    q.x = q8(v.x, inv); q.y = q8(v.y, inv); q.z = q8(v.z, inv); q.w = q8(v.w, inv);
    Tb[(size_t)row * 32 + lane] = q;
    if (lane == 0)
        meta[row] = (row < NROWS) ? make_float2(s, 2.0f * (mxs / 127.0f))
                                  : make_float2(1.0e30f, 0.0f);
}

// ---------------- query max (global per side) ----------------
__global__ void k_qmax(const int* __restrict__ imap)
{
    int z = blockIdx.y;
    const float* mapped = z ? g_ymap : g_xmap;
    int K = z ? XD : YD;
    int wid = threadIdx.x >> 5, lane = threadIdx.x & 31;
    int q = blockIdx.x * 8 + wid;
    if (q >= NQ) return;
    int row = imap[2 * q + z];
    float mx = 0.0f;
    int c = lane * 4;
    if (c < K) {
        float4 v = *(const float4*)(mapped + (size_t)row * K + c);
        mx = fmaxf(fmaxf(fabsf(v.x), fabsf(v.y)), fmaxf(fabsf(v.z), fabsf(v.w)));
    }
#pragma unroll
    for (int o = 16; o; o >>= 1) mx = fmaxf(mx, __shfl_xor_sync(0xffffffffu, mx, o));
    if (lane == 0) atomicMax(&g_sqbits[z], __float_as_uint(mx));
}

// ---------------- query quantize ----------------
__global__ void k_prep_q8(const int* __restrict__ imap)
{
    int z = blockIdx.y;
    const float* mapped = z ? g_ymap : g_xmap;
    int K = z ? XD : YD;
    char4* Qb = (char4*)(z ? g_Qb8B : g_Qb8A);
    int wid = threadIdx.x >> 5, lane = threadIdx.x & 31;
    int q = blockIdx.x * 8 + wid;
    if (q >= NQPAD) return;
    float4 v = make_float4(0.f, 0.f, 0.f, 0.f);
    if (q < NQ) {
        int row = imap[2 * q + z];
        int c = lane * 4;
        if (c < K) v = *(const float4*)(mapped + (size_t)row * K + c);
    }
    float inv = 127.0f / fmaxf(__uint_as_float(g_sqbits[z]), 1e-20f);
    char4 o;
    o.x = q8(v.x, inv); o.y = q8(v.y, inv); o.z = q8(v.z, inv); o.w = q8(v.w, inv);
    Qb[(size_t)q * 32 + lane] = o;
}

// ---------------- fused 2-layer MLP (unchanged from R12) ---------------------
__global__ __launch_bounds__(512, 1)
void k_mlp2(const float* __restrict__ X0, const float* __restrict__ X1,
            int wsel0, int wsel1,
            const float* __restrict__ b1_0, const float* __restrict__ b2_0,
            const float* __restrict__ b1_1, const float* __restrict__ b2_1,
            float* __restrict__ Y0, float* __restrict__ Y1,
            int Kin0, int Nout0, int Kin1, int Nout1)
{
    extern __shared__ __align__(16) uint32_t sm[];
    uint32_t* Xs  = sm;
    uint32_t* W1t = Xs + 128 * MP;
    uint32_t* W2t = W1t + 128 * MP;
    int tid = threadIdx.x, lane = tid & 31, wid = tid >> 5;
    int warp_m = wid >> 2, warp_n = wid & 3;
    int z = blockIdx.y;
    int m0 = blockIdx.x * 128;

    const float* X = z ? X1 : X0;
    int wsel = z ? wsel1 : wsel0;
    int Kin  = z ? Kin1 : Kin0;
    int Nout = z ? Nout1 : Nout0;
    const float* B1 = z ? b1_1 : b1_0;
    const float* B2 = z ? b2_1 : b2_0;
    float* Y = z ? Y1 : Y0;

    for (int i = tid; i < 128 * 36; i += 512) {
        int r = i / 36, c = i - r * 36;
        Xs[r * MP + 96 + c] = 0;
    }
    __syncthreads();
    {
        uint32_t sX = smem_u32(Xs);
        int chunks = Kin >> 2;
        int tot = 128 * chunks;
        for (int i = tid; i < tot; i += 512) {
            int r = i / chunks, c = i - r * chunks;
            if (m0 + r < NROWS)
                cpa16(sX + r * (MP * 4) + c * 16, X + (size_t)(m0 + r) * Kin + c * 4);
        }
        uint32_t sW = smem_u32(W1t);
        const char* wsrc = (const char*)(g_Wt + (size_t)wsel * 2 * WSTRIDE);
        for (int i = tid; i < 8448; i += 512)
            cpa16(sW + i * 16, wsrc + i * 16);
        CP_COMMIT();
        CP_WAIT0();
    }
    __syncthreads();

    int r0 = lane >> 2, c0 = lane & 3;
    float acc[2][4][4];
    int nf1max = (warp_n < 3) ? 4 : 1;
    int nf2max = (warp_n < 3) ? 4 : ((Nout > 104) ? 3 : 1);

#pragma unroll
    for (int mf = 0; mf < 2; mf++)
#pragma unroll
        for (int nf = 0; nf < 4; nf++)
#pragma unroll
            for (int r = 0; r < 4; r++) acc[mf][nf][r] = 0.0f;

    int ks1 = (Kin + 7) >> 3;
    for (int ks = 0; ks < ks1; ks++) {
        int kb = ks * 8;
        uint32_t a[2][4], b[4][2];
#pragma unroll
        for (int mf = 0; mf < 2; mf++) {
            int row = warp_m * 32 + mf * 16 + r0;
            const uint32_t* p = &Xs[row * MP + kb + c0];
            a[mf][0] = f2tf32(__uint_as_float(p[0]));
            a[mf][1] = f2tf32(__uint_as_float(p[8 * MP]));
            a[mf][2] = f2tf32(__uint_as_float(p[4]));
            a[mf][3] = f2tf32(__uint_as_float(p[8 * MP + 4]));
        }
#pragma unroll
        for (int nf = 0; nf < 4; nf++) {
            if (nf < nf1max) {
                int col = warp_n * 32 + nf * 8 + r0;
                const uint32_t* p = &W1t[col * MP + kb + c0];
                b[nf][0] = p[0]; b[nf][1] = p[4];
            }
        }
#pragma unroll
        for (int mf = 0; mf < 2; mf++)
#pragma unroll
            for (int nf = 0; nf < 4; nf++)
                if (nf < nf1max)
                    asm volatile(
                        "mma.sync.aligned.m16n8k8.row.col.f32.tf32.tf32.f32 "
                        "{%0,%1,%2,%3}, {%4,%5,%6,%7}, {%8,%9}, {%0,%1,%2,%3};"
                        : "+f"(acc[mf][nf][0]), "+f"(acc[mf][nf][1]),
                          "+f"(acc[mf][nf][2]), "+f"(acc[mf][nf][3])
                        : "r"(a[mf][0]), "r"(a[mf][1]), "r"(a[mf][2]), "r"(a[mf][3]),
                          "r"(b[nf][0]), "r"(b[nf][1]));
    }
    __syncthreads();

#pragma unroll
    for (int mf = 0; mf < 2; mf++)
#pragma unroll
        for (int nf = 0; nf < 4; nf++) {
            int row = warp_m * 32 + mf * 16 + r0;
            int col = warp_n * 32 + nf * 8 + c0 * 2;
            float bi0 = (col < HID) ? B1[col] : 0.0f;
            float bi1 = (col + 1 < HID) ? B1[col + 1] : 0.0f;
            float v0 = (col < HID) ? fmaxf(acc[mf][nf][0] + bi0, 0.0f) : 0.0f;
            float v1 = (col + 1 < HID) ? fmaxf(acc[mf][nf][1] + bi1, 0.0f) : 0.0f;
            float v2 = (col < HID) ? fmaxf(acc[mf][nf][2] + bi0, 0.0f) : 0.0f;
            float v3 = (col + 1 < HID) ? fmaxf(acc[mf][nf][3] + bi1, 0.0f) : 0.0f;
            Xs[row * MP + col]           = f2tf32(v0);
            Xs[row * MP + col + 1]       = f2tf32(v1);
            Xs[(row + 8) * MP + col]     = f2tf32(v2);
            Xs[(row + 8) * MP + col + 1] = f2tf32(v3);
        }
    __syncthreads();

#pragma unroll
    for (int mf = 0; mf < 2; mf++)
#pragma unroll
        for (int nf = 0; nf < 4; nf++)
#pragma unroll
            for (int r = 0; r < 4; r++) acc[mf][nf][r] = 0.0f;

    const int ks2 = (HID + 7) >> 3;
    for (int ks = 0; ks < ks2; ks++) {
        int kb = ks * 8;
        uint32_t a[2][4], b[4][2];
#pragma unroll
        for (int mf = 0; mf < 2; mf++) {
            int row = warp_m * 32 + mf * 16 + r0;
            const uint32_t* p = &Xs[row * MP + kb + c0];
            a[mf][0] = p[0]; a[mf][1] = p[8 * MP]; a[mf][2] = p[4]; a[mf][3] = p[8 * MP + 4];
        }
#pragma unroll
        for (int nf = 0; nf < 4; nf++) {
            if (nf < nf2max) {
                int col = warp_n * 32 + nf * 8 + r0;
                const uint32_t* p = &W2t[col * MP + kb + c0];
                b[nf][0] = p[0]; b[nf][1] = p[4];
            }
        }
#pragma unroll
        for (int mf = 0; mf < 2; mf++)
#pragma unroll
            for (int nf = 0; nf < 4; nf++)
                if (nf < nf2max)
                    asm volatile(
                        "mma.sync.aligned.m16n8k8.row.col.f32.tf32.tf32.f32 "
                        "{%0,%1,%2,%3}, {%4,%5,%6,%7}, {%8,%9}, {%0,%1,%2,%3};"
                        : "+f"(acc[mf][nf][0]), "+f"(acc[mf][nf][1]),
                          "+f"(acc[mf][nf][2]), "+f"(acc[mf][nf][3])
                        : "r"(a[mf][0]), "r"(a[mf][1]), "r"(a[mf][2]), "r"(a[mf][3]),
                          "r"(b[nf][0]), "r"(b[nf][1]));
    }

#pragma unroll
    for (int mf = 0; mf < 2; mf++)
#pragma unroll
        for (int nf = 0; nf < 4; nf++) {
            int row = warp_m * 32 + mf * 16 + r0;
            int col = warp_n * 32 + nf * 8 + c0 * 2;
            if (col < Nout) {
                float bi0 = B2[col], bi1 = (col + 1 < Nout) ? B2[col + 1] : 0.0f;
                if (m0 + row < NROWS)
                    *(float2*)&Y[(size_t)(m0 + row) * Nout + col] =
                        make_float2(acc[mf][nf][0] + bi0, acc[mf][nf][1] + bi1);
                if (m0 + row + 8 < NROWS)
                    *(float2*)&Y[(size_t)(m0 + row + 8) * Nout + col] =
                        make_float2(acc[mf][nf][2] + bi0, acc[mf][nf][3] + bi1);
            }
        }
}

// ---------------- fused reductions (unchanged) ----------------
__global__ void k_red(const int* __restrict__ imap,
                      const float* __restrict__ x_w, const float* __restrict__ y_w,
                      float* out)
{
    int y = blockIdx.y;
    int w = threadIdx.x >> 5, lane = threadIdx.x & 31;
    const float *A = 0, *B = 0;
    int Kc = 1, idx = blockIdx.x * 8 + w;
    float scale = 0.0f;
    int row_a = -1, row_b = -1;
    if (y < 2) {
        if (idx < NROWS) {
            A = y ? g_yrt : g_xrt; B = y ? y_w : x_w; Kc = y ? YD : XD;
            scale = 1.0f / NROWS;
            row_a = idx; row_b = idx;
        }
    } else {
        if (idx < NQ) {
            int z = y - 2;
            A = z ? g_ymap : g_xmap; B = z ? x_w : y_w; Kc = z ? XD : YD;
            scale = 1.0f / NQ;
            row_a = imap[2 * idx + z];
            row_b = imap[2 * idx + 1 - z];
        }
    }
    float r = 0.0f;
    if (row_a >= 0) {
        const float* a = A + (size_t)row_a * Kc;
        const float* b = B + (size_t)row_b * Kc;
        float s = 0.0f;
        for (int j = lane; j < Kc; j += 32) { float d = a[j] - b[j]; s = fmaf(d, d, s); }
#pragma unroll
        for (int o = 16; o; o >>= 1) s += __shfl_xor_sync(0xffffffffu, s, o);
        r = sqrtf(s) * scale;
    }
    __shared__ float sh[8];
    if (lane == 0) sh[w] = r;
    __syncthreads();
    if (threadIdx.x == 0) {
        float t = 0.0f;
#pragma unroll
        for (int i = 0; i < 8; i++) t += sh[i];
        if (t != 0.0f) atomicAdd(out, t);
    }
}

// ---------------- int8 IMMA 1-NN proxy-min ----------------
#define TP      144
#define SM_B0   (128 * TP)
#define SM_B1   (SM_B0 + 128 * TP)
#define SM_M0   (SM_B1 + 128 * TP)
#define SM_M1   (SM_M0 + 1024)
#define SM_MIN  (SM_M1 + 1024)
#define SMEM_NN (SM_MIN + 512)

__global__ __launch_bounds__(256, 2)
void k_nn()
{
    extern __shared__ __align__(16) char dsm[];
    int z = blockIdx.z;
    const char* Qb = z ? g_Qb8B : g_Qb8A;
    const char* Tb = z ? g_Tb8B : g_Tb8A;
    const float2* meta = z ? g_metaB : g_metaA;
    unsigned* mb = z ? g_mbB : g_mbA;
    float sqs = __uint_as_float(g_sqbits[z]) * (1.0f / 127.0f);

    uint32_t sbase = smem_u32(dsm);
    unsigned* smin = (unsigned*)(dsm + SM_MIN);
    int tid = threadIdx.x, lane = tid & 31, wid = tid >> 5;
    int warp_m = wid >> 2, warp_n = wid & 3;
    int qtile = blockIdx.x, g = blockIdx.y;
    int ch0 = g * NCH_PER;

    {   // A tile (128 rows x 128B) + B chunk 0 + meta 0
        const char* Ag = Qb + (size_t)qtile * 16384;
        const char* Bg = Tb + (size_t)ch0 * 16384;
        for (int i = tid; i < 1024; i += 256) {
            int row = i >> 3, c16 = (i & 7) * 16;
            cpa16(sbase + row * TP + c16, Ag + row * 128 + c16);
            cpa16(sbase + SM_B0 + row * TP + c16, Bg + row * 128 + c16);
        }
        const char* Mg = (const char*)(meta + (size_t)ch0 * 128);
        for (int i = tid; i < 64; i += 256)
            cpa16(sbase + SM_M0 + i * 16, Mg + i * 16);
        CP_COMMIT();
    }
    if (tid < 128) smin[tid] = 0xFFFFFFFFu;

    float best0[4], best1[4];
#pragma unroll
    for (int mf = 0; mf < 4; mf++) { best0[mf] = 1e30f; best1[mf] = 1e30f; }

    uint32_t aAddr = sbase + (uint32_t)((warp_m * 64 + (lane & 15)) * TP
                                        + ((lane >> 4) & 1) * 16);
    uint32_t bOff  = (uint32_t)((warp_n * 32 + (lane & 7)) * TP
                                + ((lane >> 3) & 1) * 16);

    for (int c = 0; c < NCH_PER; c++) {
        CP_WAIT0();
        __syncthreads();
        if (c + 1 < NCH_PER) {
            const char* Bg = Tb + (size_t)(ch0 + c + 1) * 16384;
            uint32_t dstb = sbase + (((c + 1) & 1) ? SM_B1 : SM_B0);
            for (int i = tid; i < 1024; i += 256) {
                int row = i >> 3, c16 = (i & 7) * 16;
                cpa16(dstb + row * TP + c16, Bg + row * 128 + c16);
            }
            const char* Mg = (const char*)(meta + (size_t)(ch0 + c + 1) * 128);
            uint32_t dstm = sbase + (((c + 1) & 1) ? SM_M1 : SM_M0);
            for (int i = tid; i < 64; i += 256)
                cpa16(dstm + i * 16, Mg + i * 16);
            CP_COMMIT();
        }
        uint32_t bAddr = sbase + ((c & 1) ? SM_B1 : SM_B0) + bOff;
        const float2* mS = (const float2*)(dsm + ((c & 1) ? SM_M1 : SM_M0));

        int acc[4][4][4];
#pragma unroll
        for (int mf = 0; mf < 4; mf++)
#pragma unroll
            for (int nf = 0; nf < 4; nf++)
#pragma unroll
                for (int r = 0; r < 4; r++) acc[mf][nf][r] = 0;

#pragma unroll
        for (int ks = 0; ks < 4; ks++) {      // K = 128 = 4 x k32
            uint32_t a[4][4], b[4][2];
#pragma unroll
            for (int mf = 0; mf < 4; mf++)
                asm volatile(
                    "ldmatrix.sync.aligned.m8n8.x4.shared.b16 {%0,%1,%2,%3}, [%4];"
                    : "=r"(a[mf][0]), "=r"(a[mf][1]), "=r"(a[mf][2]), "=r"(a[mf][3])
                    : "r"(aAddr + mf * 16 * TP + ks * 32));
#pragma unroll
            for (int nf = 0; nf < 4; nf++)
                asm volatile(
                    "ldmatrix.sync.aligned.m8n8.x2.shared.b16 {%0,%1}, [%2];"
                    : "=r"(b[nf][0]), "=r"(b[nf][1])
                    : "r"(bAddr + nf * 8 * TP + ks * 32));
#pragma unroll
            for (int mf = 0; mf < 4; mf++)
#pragma unroll
                for (int nf = 0; nf < 4; nf++)
                    asm volatile(
                        "mma.sync.aligned.m16n8k32.row.col.s32.s8.s8.s32 "
                        "{%0,%1,%2,%3}, {%4,%5,%6,%7}, {%8,%9}, {%0,%1,%2,%3};"
                        : "+r"(acc[mf][nf][0]), "+r"(acc[mf][nf][1]),
                          "+r"(acc[mf][nf][2]), "+r"(acc[mf][nf][3])
                        : "r"(a[mf][0]), "r"(a[mf][1]), "r"(a[mf][2]), "r"(a[mf][3]),
                          "r"(b[nf][0]), "r"(b[nf][1]));
        }
        // epilogue: p = tn[c] - (sqs * st2[c]) * dot ; fold into per-row best
#pragma unroll
        for (int nf = 0; nf < 4; nf++) {
            int cl = warp_n * 32 + nf * 8 + (lane & 3) * 2;
            float2 m0 = mS[cl], m1 = mS[cl + 1];
            float k0 = sqs * m0.y, k1 = sqs * m1.y;
#pragma unroll
            for (int mf = 0; mf < 4; mf++) {
                float p0 = fmaf(-k0, (float)acc[mf][nf][0], m0.x);
                float p1 = fmaf(-k1, (float)acc[mf][nf][1], m1.x);
                float p2 = fmaf(-k0, (float)acc[mf][nf][2], m0.x);
                float p3 = fmaf(-k1, (float)acc[mf][nf][3], m1.x);
                best0[mf] = fminf(best0[mf], fminf(p0, p1));
                best1[mf] = fminf(best1[mf], fminf(p2, p3));
            }
        }
        __syncthreads();   // meta smem reused next iter
    }

#pragma unroll
    for (int mf = 0; mf < 4; mf++) {
        float v0 = best0[mf], v1 = best1[mf];
        v0 = fminf(v0, __shfl_xor_sync(0xffffffffu, v0, 1));
        v0 = fminf(v0, __shfl_xor_sync(0xffffffffu, v0, 2));
        v1 = fminf(v1, __shfl_xor_sync(0xffffffffu, v1, 1));
        v1 = fminf(v1, __shfl_xor_sync(0xffffffffu, v1, 2));
        if ((lane & 3) == 0) {
            int r = warp_m * 64 + mf * 16 + (lane >> 2);
            atomicMin(&smin[r], enc(v0));
            atomicMin(&smin[r + 8], enc(v1));
        }
    }
    __syncthreads();
    if (tid < 128) {
        int q = qtile * 128 + tid;
        if (q < NQ) atomicMin(&mb[q], smin[tid]);
    }
}

// ---------------- finalize: exact same int8 proxy at idx ----------------
__global__ void k_finish(const int* __restrict__ imap, float scale, float* out)
{
    int z = blockIdx.y;
    const char* Qb = z ? g_Qb8B : g_Qb8A;
    const char* Tb = z ? g_Tb8B : g_Tb8A;
    const float2* meta = z ? g_metaB : g_metaA;
    const unsigned* mb = z ? g_mbB : g_mbA;
    float sqs = __uint_as_float(g_sqbits[z]) * (1.0f / 127.0f);
    int w = threadIdx.x >> 5, lane = threadIdx.x & 31;
    int q = blockIdx.x * 8 + w;
    float c = 0.0f;
    if (q < NQ) {
        int t = imap[2 * q + z];
        int q4 = ((const int*)(Qb + (size_t)q * 128))[lane];
        int t4 = ((const int*)(Tb + (size_t)t * 128))[lane];
        int dot = __dp4a(q4, t4, 0);
#pragma unroll
        for (int o = 16; o; o >>= 1) dot += __shfl_xor_sync(0xffffffffu, dot, o);
        if (lane == 0) {
            float2 m = meta[t];
            float k = sqs * m.y;
            float p = fmaf(-k, (float)dot, m.x);
            if (mb[q] < enc(p)) c = 1.0f;
        }
    }
    __shared__ float sh[8];
    if (lane == 0) sh[w] = c;
    __syncthreads();
    if (threadIdx.x == 0) {
        float t = 0.0f;
#pragma unroll
        for (int i = 0; i < 8; i++) t += sh[i];
        if (t != 0.0f) atomicAdd(out, t * scale);
    }
}

// ---------------- host ----------------
extern "C" void kernel_launch(void* const* d_in, const int* in_sizes, int n_in,
                              void* d_out, int out_size)
{
    const float* x_w   = (const float*)d_in[0];
    const float* y_w   = (const float*)d_in[1];
    const float* fx_w1 = (const float*)d_in[2];
    const float* fx_b1 = (const float*)d_in[3];
    const float* fx_w2 = (const float*)d_in[4];
    const float* fx_b2 = (const float*)d_in[5];
    const float* gy_w1 = (const float*)d_in[6];
    const float* gy_b1 = (const float*)d_in[7];
    const float* gy_w2 = (const float*)d_in[8];
    const float* gy_b2 = (const float*)d_in[9];
    const int*   imap  = (const int*)d_in[10];
    float* out = (float*)d_out;

    float *xmap, *ymap, *xrt, *yrt;
    cudaGetSymbolAddress((void**)&xmap, g_xmap);
    cudaGetSymbolAddress((void**)&ymap, g_ymap);
    cudaGetSymbolAddress((void**)&xrt,  g_xrt);
    cudaGetSymbolAddress((void**)&yrt,  g_yrt);

    static int smemSet = 0;
    if (!smemSet) {
        cudaFuncSetAttribute(k_nn, cudaFuncAttributeMaxDynamicSharedMemorySize, SMEM_NN);
        cudaFuncSetAttribute(k_mlp2, cudaFuncAttributeMaxDynamicSharedMemorySize,
                             3 * 128 * MP * 4);
        smemSet = 1;
    }

    k_init<<<32, 256>>>(out);
    k_wprep<<<(4 * WSTRIDE + 255) / 256, 256>>>(fx_w1, fx_w2, gy_w1, gy_w2);
    {
        dim3 tg((NTPAD + 7) / 8, 2);
        k_prep_t8<<<tg, 256>>>(x_w, y_w);
    }
    int mlpSmem = 3 * 128 * MP * 4;
    dim3 mg((NROWS + 127) / 128, 2);
    k_mlp2<<<mg, 512, mlpSmem>>>(x_w, y_w, 0, 1, fx_b1, fx_b2, gy_b1, gy_b2,
                                 xmap, ymap, XD, YD, YD, XD);
    k_mlp2<<<mg, 512, mlpSmem>>>(xmap, ymap, 1, 0, gy_b1, gy_b2, fx_b1, fx_b2,
                                 xrt, yrt, YD, XD, XD, YD);

    {
        dim3 rg((NROWS + 7) / 8, 4);
        k_red<<<rg, 256>>>(imap, x_w, y_w, out);
    }
    {
        dim3 qm((NQ + 7) / 8, 2);
        k_qmax<<<qm, 256>>>(imap);
        dim3 qg((NQPAD + 7) / 8, 2);
        k_prep_q8<<<qg, 256>>>(imap);
    }
    {
        dim3 ng(QTILES, GSPLIT, 2);
        k_nn<<<ng, 256, SMEM_NN>>>();
    }
    {
        dim3 eg((NQ + 7) / 8, 2);
        k_finish<<<eg, 256>>>(imap, 1.0f / NQ, out);
    }
}

// round 14
// speedup vs baseline: 2.3839x; 2.3839x over previous
#include <cuda_runtime.h>
#include <cuda_bf16.h>
#include <math.h>
#include <stdint.h>

// ---------------- problem constants ----------------
#define NROWS 25000
#define NQ    8000
#define XD    100
#define YD    120
#define HID   100
#define KP    128
#define NQPAD 8064          // 63*128
#define NTPAD 25088         // 196*128
#define QTILES 63
#define GSPLIT 14
#define NCH_PER 14
#define CSHIFT 8.0f
#define MP    132
#define WSTRIDE (128 * MP)

// ---------------- scratch ----------------
__device__ __align__(16) float g_xmap[NROWS * YD];
__device__ __align__(16) float g_ymap[NROWS * XD];
__device__ __align__(16) float g_xrt [NROWS * XD];
__device__ __align__(16) float g_yrt [NROWS * YD];
__device__ uint32_t g_Wt[4 * WSTRIDE];
__device__ __align__(16) __nv_bfloat16 g_QbA[NQPAD * KP];
__device__ __align__(16) __nv_bfloat16 g_QbB[NQPAD * KP];
__device__ __align__(16) __nv_bfloat16 g_TbA[NTPAD * KP];
__device__ __align__(16) __nv_bfloat16 g_TbB[NTPAD * KP];
__device__ unsigned int g_mbA[NQ];
__device__ unsigned int g_mbB[NQ];

// ---------------- helpers ----------------
__device__ __forceinline__ uint32_t smem_u32(const void* p) {
    uint32_t a;
    asm("{ .reg .u64 t; cvta.to.shared.u64 t, %1; cvt.u32.u64 %0, t; }" : "=r"(a) : "l"(p));
    return a;
}
__device__ __forceinline__ void cpa16(uint32_t dst, const void* src) {
    asm volatile("cp.async.cg.shared.global [%0], [%1], 16;" :: "r"(dst), "l"(src));
}
#define CP_COMMIT() asm volatile("cp.async.commit_group;" ::: "memory")
#define CP_WAIT0()  asm volatile("cp.async.wait_group 0;" ::: "memory")

__device__ __forceinline__ uint32_t f2tf32(float v) {
    uint32_t r;
    asm("cvt.rna.tf32.f32 %0, %1;" : "=r"(r) : "f"(v));
    return r;
}

// ---------------- init ----------------
__global__ void k_init(float* out) {
    int i = blockIdx.x * 256 + threadIdx.x;
    if (i == 0) out[0] = 0.0f;
    if (i < NQ) { g_mbA[i] = 0x7F800000u; g_mbB[i] = 0x7F800000u; }
}

// ---------------- weight prep (transposed, tf32 RNA, pitch MP) --------------
__global__ void k_wprep(const float* __restrict__ w0, const float* __restrict__ w1,
                        const float* __restrict__ w2, const float* __restrict__ w3)
{
    int idx = blockIdx.x * 256 + threadIdx.x;
    if (idx >= 4 * WSTRIDE) return;
    int m = idx / WSTRIDE, r = idx - m * WSTRIDE;
    int n = r / MP, k = r - n * MP;
    const float* src; int Kd, Nd;
    if (m == 0)      { src = w0; Kd = XD;  Nd = HID; }
    else if (m == 1) { src = w1; Kd = HID; Nd = YD;  }
    else if (m == 2) { src = w2; Kd = YD;  Nd = HID; }
    else             { src = w3; Kd = HID; Nd = XD;  }
    float v = (n < Nd && k < Kd) ? src[k * Nd + n] : 0.0f;
    g_Wt[idx] = f2tf32(v);
}

// ---------------- target prep (bf16 + folded tn, warp-cooperative) ----------
__global__ void k_prep_t(const float* __restrict__ x_w, const float* __restrict__ y_w)
{
    int z = blockIdx.y;
    const float* T = z ? x_w : y_w;
    int K = z ? XD : YD;
    __nv_bfloat16* Tb = z ? g_TbB : g_TbA;
    int tid = threadIdx.x, lane = tid & 31, wid = tid >> 5;
    int idx = blockIdx.x * 256 + tid;              // 2 rows per block
    int row = idx >> 7, col = idx & 127;
    bool rok = row < NROWS;
    float v = (rok && col < K) ? T[(size_t)row * K + col] : 0.0f;

    float s = v * v;
#pragma unroll
    for (int o = 16; o; o >>= 1) s += __shfl_xor_sync(0xffffffffu, s, o);
    __shared__ float sh[8];
    if (lane == 0) sh[wid] = s;
    __syncthreads();
    int rw = (tid >> 7) * 4;
    float tot = sh[rw] + sh[rw + 1] + sh[rw + 2] + sh[rw + 3] + CSHIFT;

    float o = v;
    if (col == K)          o = rok ? tot : 1.0e6f;
    else if (col == K + 1) o = rok ? (tot - __bfloat162float(__float2bfloat16(tot))) : 0.0f;
    Tb[idx] = __float2bfloat16(o);
}

// ---------------- fused 2-layer MLP: raw-X load, smem weights, RNA rounding --
__global__ __launch_bounds__(512, 1)
void k_mlp2(const float* __restrict__ X0, const float* __restrict__ X1,
            int wsel0, int wsel1,
            const float* __restrict__ b1_0, const float* __restrict__ b2_0,
            const float* __restrict__ b1_1, const float* __restrict__ b2_1,
            float* __restrict__ Y0, float* __restrict__ Y1,
            int Kin0, int Nout0, int Kin1, int Nout1)
{
    extern __shared__ __align__(16) uint32_t sm[];
    uint32_t* Xs  = sm;
    uint32_t* W1t = Xs + 128 * MP;
    uint32_t* W2t = W1t + 128 * MP;
    int tid = threadIdx.x, lane = tid & 31, wid = tid >> 5;
    int warp_m = wid >> 2, warp_n = wid & 3;
    int z = blockIdx.y;
    int m0 = blockIdx.x * 128;

    const float* X = z ? X1 : X0;
    int wsel = z ? wsel1 : wsel0;
    int Kin  = z ? Kin1 : Kin0;
    int Nout = z ? Nout1 : Nout0;
    const float* B1 = z ? b1_1 : b1_0;
    const float* B2 = z ? b2_1 : b2_0;
    float* Y = z ? Y1 : Y0;

    for (int i = tid; i < 128 * 36; i += 512) {
        int r = i / 36, c = i - r * 36;
        Xs[r * MP + 96 + c] = 0;
    }
    __syncthreads();
    {
        uint32_t sX = smem_u32(Xs);
        int chunks = Kin >> 2;
        int tot = 128 * chunks;
        for (int i = tid; i < tot; i += 512) {
            int r = i / chunks, c = i - r * chunks;
            if (m0 + r < NROWS)
                cpa16(sX + r * (MP * 4) + c * 16, X + (size_t)(m0 + r) * Kin + c * 4);
        }
        uint32_t sW = smem_u32(W1t);
        const char* wsrc = (const char*)(g_Wt + (size_t)wsel * 2 * WSTRIDE);
        for (int i = tid; i < 8448; i += 512)
            cpa16(sW + i * 16, wsrc + i * 16);
        CP_COMMIT();
        CP_WAIT0();
    }
    __syncthreads();

    int r0 = lane >> 2, c0 = lane & 3;
    float acc[2][4][4];
    int nf1max = (warp_n < 3) ? 4 : 1;
    int nf2max = (warp_n < 3) ? 4 : ((Nout > 104) ? 3 : 1);

    // ---------------- stage 1 (A-fragments RNA-rounded from raw fp32) -------
#pragma unroll
    for (int mf = 0; mf < 2; mf++)
#pragma unroll
        for (int nf = 0; nf < 4; nf++)
#pragma unroll
            for (int r = 0; r < 4; r++) acc[mf][nf][r] = 0.0f;

    int ks1 = (Kin + 7) >> 3;
    for (int ks = 0; ks < ks1; ks++) {
        int kb = ks * 8;
        uint32_t a[2][4], b[4][2];
#pragma unroll
        for (int mf = 0; mf < 2; mf++) {
            int row = warp_m * 32 + mf * 16 + r0;
            const uint32_t* p = &Xs[row * MP + kb + c0];
            a[mf][0] = f2tf32(__uint_as_float(p[0]));
            a[mf][1] = f2tf32(__uint_as_float(p[8 * MP]));
            a[mf][2] = f2tf32(__uint_as_float(p[4]));
            a[mf][3] = f2tf32(__uint_as_float(p[8 * MP + 4]));
        }
#pragma unroll
        for (int nf = 0; nf < 4; nf++) {
            if (nf < nf1max) {
                int col = warp_n * 32 + nf * 8 + r0;
                const uint32_t* p = &W1t[col * MP + kb + c0];
                b[nf][0] = p[0]; b[nf][1] = p[4];
            }
        }
#pragma unroll
        for (int mf = 0; mf < 2; mf++)
#pragma unroll
            for (int nf = 0; nf < 4; nf++)
                if (nf < nf1max)
                    asm volatile(
                        "mma.sync.aligned.m16n8k8.row.col.f32.tf32.tf32.f32 "
                        "{%0,%1,%2,%3}, {%4,%5,%6,%7}, {%8,%9}, {%0,%1,%2,%3};"
                        : "+f"(acc[mf][nf][0]), "+f"(acc[mf][nf][1]),
                          "+f"(acc[mf][nf][2]), "+f"(acc[mf][nf][3])
                        : "r"(a[mf][0]), "r"(a[mf][1]), "r"(a[mf][2]), "r"(a[mf][3]),
                          "r"(b[nf][0]), "r"(b[nf][1]));
    }
    __syncthreads();

    // H = relu(acc + b1), RNA tf32, back into Xs (cols >= HID zeroed)
#pragma unroll
    for (int mf = 0; mf < 2; mf++)
#pragma unroll
        for (int nf = 0; nf < 4; nf++) {
            int row = warp_m * 32 + mf * 16 + r0;
            int col = warp_n * 32 + nf * 8 + c0 * 2;
            float bi0 = (col < HID) ? B1[col] : 0.0f;
            float bi1 = (col + 1 < HID) ? B1[col + 1] : 0.0f;
            float v0 = (col < HID) ? fmaxf(acc[mf][nf][0] + bi0, 0.0f) : 0.0f;
            float v1 = (col + 1 < HID) ? fmaxf(acc[mf][nf][1] + bi1, 0.0f) : 0.0f;
            float v2 = (col < HID) ? fmaxf(acc[mf][nf][2] + bi0, 0.0f) : 0.0f;
            float v3 = (col + 1 < HID) ? fmaxf(acc[mf][nf][3] + bi1, 0.0f) : 0.0f;
            Xs[row * MP + col]           = f2tf32(v0);
            Xs[row * MP + col + 1]       = f2tf32(v1);
            Xs[(row + 8) * MP + col]     = f2tf32(v2);
            Xs[(row + 8) * MP + col + 1] = f2tf32(v3);
        }
    __syncthreads();

    // ---------------- stage 2 (H already tf32) ----------------
#pragma unroll
    for (int mf = 0; mf < 2; mf++)
#pragma unroll
        for (int nf = 0; nf < 4; nf++)
#pragma unroll
            for (int r = 0; r < 4; r++) acc[mf][nf][r] = 0.0f;

    const int ks2 = (HID + 7) >> 3;
    for (int ks = 0; ks < ks2; ks++) {
        int kb = ks * 8;
        uint32_t a[2][4], b[4][2];
#pragma unroll
        for (int mf = 0; mf < 2; mf++) {
            int row = warp_m * 32 + mf * 16 + r0;
            const uint32_t* p = &Xs[row * MP + kb + c0];
            a[mf][0] = p[0]; a[mf][1] = p[8 * MP]; a[mf][2] = p[4]; a[mf][3] = p[8 * MP + 4];
        }
#pragma unroll
        for (int nf = 0; nf < 4; nf++) {
            if (nf < nf2max) {
                int col = warp_n * 32 + nf * 8 + r0;
                const uint32_t* p = &W2t[col * MP + kb + c0];
                b[nf][0] = p[0]; b[nf][1] = p[4];
            }
        }
#pragma unroll
        for (int mf = 0; mf < 2; mf++)
#pragma unroll
            for (int nf = 0; nf < 4; nf++)
                if (nf < nf2max)
                    asm volatile(
                        "mma.sync.aligned.m16n8k8.row.col.f32.tf32.tf32.f32 "
                        "{%0,%1,%2,%3}, {%4,%5,%6,%7}, {%8,%9}, {%0,%1,%2,%3};"
                        : "+f"(acc[mf][nf][0]), "+f"(acc[mf][nf][1]),
                          "+f"(acc[mf][nf][2]), "+f"(acc[mf][nf][3])
                        : "r"(a[mf][0]), "r"(a[mf][1]), "r"(a[mf][2]), "r"(a[mf][3]),
                          "r"(b[nf][0]), "r"(b[nf][1]));
    }

    // epilogue: bias + store fp32
#pragma unroll
    for (int mf = 0; mf < 2; mf++)
#pragma unroll
        for (int nf = 0; nf < 4; nf++) {
            int row = warp_m * 32 + mf * 16 + r0;
            int col = warp_n * 32 + nf * 8 + c0 * 2;
            if (col < Nout) {
                float bi0 = B2[col], bi1 = (col + 1 < Nout) ? B2[col + 1] : 0.0f;
                if (m0 + row < NROWS)
                    *(float2*)&Y[(size_t)(m0 + row) * Nout + col] =
                        make_float2(acc[mf][nf][0] + bi0, acc[mf][nf][1] + bi1);
                if (m0 + row + 8 < NROWS)
                    *(float2*)&Y[(size_t)(m0 + row + 8) * Nout + col] =
                        make_float2(acc[mf][nf][2] + bi0, acc[mf][nf][3] + bi1);
            }
        }
}

// ---------------- fused reductions: rnd (y=0,1), sup (y=2,3) ----------------
__global__ void k_red(const int* __restrict__ imap,
                      const float* __restrict__ x_w, const float* __restrict__ y_w,
                      float* out)
{
    int y = blockIdx.y;
    int w = threadIdx.x >> 5, lane = threadIdx.x & 31;
    const float *A = 0, *B = 0;
    int Kc = 1, idx = blockIdx.x * 8 + w;
    float scale = 0.0f;
    int row_a = -1, row_b = -1;
    if (y < 2) {
        if (idx < NROWS) {
            A = y ? g_yrt : g_xrt; B = y ? y_w : x_w; Kc = y ? YD : XD;
            scale = 1.0f / NROWS;
            row_a = idx; row_b = idx;
        }
    } else {
        if (idx < NQ) {
            int z = y - 2;
            A = z ? g_ymap : g_xmap; B = z ? x_w : y_w; Kc = z ? XD : YD;
            scale = 1.0f / NQ;
            row_a = imap[2 * idx + z];
            row_b = imap[2 * idx + 1 - z];
        }
    }
    float r = 0.0f;
    if (row_a >= 0) {
        const float* a = A + (size_t)row_a * Kc;
        const float* b = B + (size_t)row_b * Kc;
        float s = 0.0f;
        for (int j = lane; j < Kc; j += 32) { float d = a[j] - b[j]; s = fmaf(d, d, s); }
#pragma unroll
        for (int o = 16; o; o >>= 1) s += __shfl_xor_sync(0xffffffffu, s, o);
        r = sqrtf(s) * scale;
    }
    __shared__ float sh[8];
    if (lane == 0) sh[w] = r;
    __syncthreads();
    if (threadIdx.x == 0) {
        float t = 0.0f;
#pragma unroll
        for (int i = 0; i < 8; i++) t += sh[i];
        if (t != 0.0f) atomicAdd(out, t);
    }
}

// ---------------- bf16 query prep ----------------
__global__ void k_prep_q(const int* __restrict__ imap)
{
    int z = blockIdx.y;
    const float* mapped = z ? g_ymap : g_xmap;
    int K = z ? XD : YD;
    __nv_bfloat16* Qb = z ? g_QbB : g_QbA;
    int idx = blockIdx.x * 256 + threadIdx.x;
    if (idx >= NQPAD * KP) return;
    int row = idx >> 7, col = idx & 127;
    float v = 0.0f;
    if (row < NQ) {
        if (col < K) v = -2.0f * mapped[(size_t)imap[2 * row + z] * K + col];
        else if (col <= K + 1) v = 1.0f;
    }
    Qb[idx] = __float2bfloat16(v);
}

// ---------------- mma.sync 1-NN proxy-min (128-query tiles) ------------------
#define PITCH_B 272
#define SM_B0   (128 * PITCH_B)
#define SM_B1   (SM_B0 + 128 * PITCH_B)
#define SM_MIN  (SM_B1 + 128 * PITCH_B)
#define SMEM_NN (SM_MIN + 512)

template <int NKS>
__device__ __forceinline__ void nn_side(const char* __restrict__ Qb,
                                        const char* __restrict__ Tb,
                                        unsigned* __restrict__ mb,
                                        char* dsm)
{
    constexpr int NC16 = NKS * 2;
    uint32_t sbase = smem_u32(dsm);
    unsigned* smin = (unsigned*)(dsm + SM_MIN);
    int tid = threadIdx.x, lane = tid & 31, wid = tid >> 5;
    int warp_m = wid >> 2, warp_n = wid & 3;
    int qtile = blockIdx.x, g = blockIdx.y;

    {
        const char* Ag = Qb + (size_t)qtile * 32768;
        const char* Bg = Tb + (size_t)(g * NCH_PER) * 32768;
        for (int i = tid; i < 2048; i += 256) {
            int row = i >> 4, c16 = i & 15;
            if (c16 < NC16) {
                cpa16(sbase + row * PITCH_B + c16 * 16, Ag + row * 256 + c16 * 16);
                cpa16(sbase + SM_B0 + row * PITCH_B + c16 * 16, Bg + row * 256 + c16 * 16);
            }
        }
        CP_COMMIT();
    }
    if (tid < 128) smin[tid] = 0x7F800000u;

    float best0[4], best1[4];
#pragma unroll
    for (int mf = 0; mf < 4; mf++) { best0[mf] = 1e30f; best1[mf] = 1e30f; }

    uint32_t aAddr = sbase + (uint32_t)((warp_m * 64 + (lane & 15)) * PITCH_B
                                        + ((lane >> 4) & 1) * 16);
    uint32_t bOff  = (uint32_t)((warp_n * 32 + (lane & 7)) * PITCH_B
                                + ((lane >> 3) & 1) * 16);

    for (int c = 0; c < NCH_PER; c++) {
        CP_WAIT0();
        __syncthreads();
        if (c + 1 < NCH_PER) {
            const char* Bg = Tb + (size_t)(g * NCH_PER + c + 1) * 32768;
            uint32_t dstb = sbase + (((c + 1) & 1) ? SM_B1 : SM_B0);
            for (int i = tid; i < 2048; i += 256) {
                int row = i >> 4, c16 = i & 15;
                if (c16 < NC16)
                    cpa16(dstb + row * PITCH_B + c16 * 16, Bg + row * 256 + c16 * 16);
            }
            CP_COMMIT();
        }
        uint32_t bAddr = sbase + ((c & 1) ? SM_B1 : SM_B0) + bOff;

        float acc[4][4][4];
#pragma unroll
        for (int mf = 0; mf < 4; mf++)
#pragma unroll
            for (int nf = 0; nf < 4; nf++)
#pragma unroll
                for (int r = 0; r < 4; r++) acc[mf][nf][r] = 0.0f;

#pragma unroll
        for (int ks = 0; ks < NKS; ks++) {
            uint32_t a[4][4], b[4][2];
#pragma unroll
            for (int mf = 0; mf < 4; mf++)
                asm volatile(
                    "ldmatrix.sync.aligned.m8n8.x4.shared.b16 {%0,%1,%2,%3}, [%4];"
                    : "=r"(a[mf][0]), "=r"(a[mf][1]), "=r"(a[mf][2]), "=r"(a[mf][3])
                    : "r"(aAddr + mf * 16 * PITCH_B + ks * 32));
#pragma unroll
            for (int nf = 0; nf < 4; nf++)
                asm volatile(
                    "ldmatrix.sync.aligned.m8n8.x2.shared.b16 {%0,%1}, [%2];"
                    : "=r"(b[nf][0]), "=r"(b[nf][1])
                    : "r"(bAddr + nf * 8 * PITCH_B + ks * 32));
#pragma unroll
            for (int mf = 0; mf < 4; mf++)
#pragma unroll
                for (int nf = 0; nf < 4; nf++)
                    asm volatile(
                        "mma.sync.aligned.m16n8k16.row.col.f32.bf16.bf16.f32 "
                        "{%0,%1,%2,%3}, {%4,%5,%6,%7}, {%8,%9}, {%0,%1,%2,%3};"
                        : "+f"(acc[mf][nf][0]), "+f"(acc[mf][nf][1]),
                          "+f"(acc[mf][nf][2]), "+f"(acc[mf][nf][3])
                        : "r"(a[mf][0]), "r"(a[mf][1]), "r"(a[mf][2]), "r"(a[mf][3]),
                          "r"(b[nf][0]), "r"(b[nf][1]));
        }
#pragma unroll
        for (int mf = 0; mf < 4; mf++)
#pragma unroll
            for (int nf = 0; nf < 4; nf++) {
                best0[mf] = fminf(best0[mf], fminf(acc[mf][nf][0], acc[mf][nf][1]));
                best1[mf] = fminf(best1[mf], fminf(acc[mf][nf][2], acc[mf][nf][3]));
            }
    }

#pragma unroll
    for (int mf = 0; mf < 4; mf++) {
        float v0 = best0[mf], v1 = best1[mf];
        v0 = fminf(v0, __shfl_xor_sync(0xffffffffu, v0, 1));
        v0 = fminf(v0, __shfl_xor_sync(0xffffffffu, v0, 2));
        v1 = fminf(v1, __shfl_xor_sync(0xffffffffu, v1, 1));
        v1 = fminf(v1, __shfl_xor_sync(0xffffffffu, v1, 2));
        if ((lane & 3) == 0) {
            int r = warp_m * 64 + mf * 16 + (lane >> 2);
            atomicMin(&smin[r], __float_as_uint(v0));
            atomicMin(&smin[r + 8], __float_as_uint(v1));
        }
    }
    __syncthreads();
    if (tid < 128) {
        int q = qtile * 128 + tid;
        if (q < NQ) atomicMin(&mb[q], smin[tid]);
    }
}

__global__ __launch_bounds__(256, 2)
void k_nn()
{
    extern __shared__ __align__(16) char dsm[];
    if (blockIdx.z == 0)
        nn_side<8>((const char*)g_QbA, (const char*)g_TbA, g_mbA, dsm);
    else
        nn_side<7>((const char*)g_QbB, (const char*)g_TbB, g_mbB, dsm);
}

// ---------------- finalize: inline pref dot + indicator ----------------
__global__ void k_finish(const int* __restrict__ imap, float scale, float* out)
{
    int z = blockIdx.y;
    const __nv_bfloat16* Qb = z ? g_QbB : g_QbA;
    const __nv_bfloat16* Tb = z ? g_TbB : g_TbA;
    const unsigned* mb = z ? g_mbB : g_mbA;
    int w = threadIdx.x >> 5, lane = threadIdx.x & 31;
    int q = blockIdx.x * 8 + w;
    float c = 0.0f;
    if (q < NQ) {
        int t = imap[2 * q + z];
        const __nv_bfloat16* qr = Qb + (size_t)q * KP;
        const __nv_bfloat16* tr = Tb + (size_t)t * KP;
        float s = 0.0f;
#pragma unroll
        for (int k = lane; k < KP; k += 32)
            s = fmaf(__bfloat162float(qr[k]), __bfloat162float(tr[k]), s);
#pragma unroll
        for (int o = 16; o; o >>= 1) s += __shfl_xor_sync(0xffffffffu, s, o);
        if (lane == 0) {
            float m = __uint_as_float(mb[q]);
            if (m < s - 1e-4f) c = 1.0f;
        }
    }
    __shared__ float sh[8];
    if (lane == 0) sh[w] = c;
    __syncthreads();
    if (threadIdx.x == 0) {
        float t = 0.0f;
#pragma unroll
        for (int i = 0; i < 8; i++) t += sh[i];
        if (t != 0.0f) atomicAdd(out, t * scale);
    }
}

// ---------------- host ----------------
extern "C" void kernel_launch(void* const* d_in, const int* in_sizes, int n_in,
                              void* d_out, int out_size)
{
    const float* x_w   = (const float*)d_in[0];
    const float* y_w   = (const float*)d_in[1];
    const float* fx_w1 = (const float*)d_in[2];
    const float* fx_b1 = (const float*)d_in[3];
    const float* fx_w2 = (const float*)d_in[4];
    const float* fx_b2 = (const float*)d_in[5];
    const float* gy_w1 = (const float*)d_in[6];
    const float* gy_b1 = (const float*)d_in[7];
    const float* gy_w2 = (const float*)d_in[8];
    const float* gy_b2 = (const float*)d_in[9];
    const int*   imap  = (const int*)d_in[10];
    float* out = (float*)d_out;

    float *xmap, *ymap, *xrt, *yrt;
    cudaGetSymbolAddress((void**)&xmap, g_xmap);
    cudaGetSymbolAddress((void**)&ymap, g_ymap);
    cudaGetSymbolAddress((void**)&xrt,  g_xrt);
    cudaGetSymbolAddress((void**)&yrt,  g_yrt);

    static int smemSet = 0;
    if (!smemSet) {
        cudaFuncSetAttribute(k_nn, cudaFuncAttributeMaxDynamicSharedMemorySize, SMEM_NN);
        cudaFuncSetAttribute(k_mlp2, cudaFuncAttributeMaxDynamicSharedMemorySize,
                             3 * 128 * MP * 4);
        smemSet = 1;
    }

    k_init<<<32, 256>>>(out);
    k_wprep<<<(4 * WSTRIDE + 255) / 256, 256>>>(fx_w1, fx_w2, gy_w1, gy_w2);
    {
        dim3 tg((NTPAD * KP) / 256, 2);
        k_prep_t<<<tg, 256>>>(x_w, y_w);
    }
    int mlpSmem = 3 * 128 * MP * 4;
    dim3 mg((NROWS + 127) / 128, 2);
    // launch1: z=0 fx(x_w)->xmap ; z=1 gy(y_w)->ymap
    k_mlp2<<<mg, 512, mlpSmem>>>(x_w, y_w, 0, 1, fx_b1, fx_b2, gy_b1, gy_b2,
                                 xmap, ymap, XD, YD, YD, XD);
    // launch2: z=0 gy(xmap)->xrt ; z=1 fx(ymap)->yrt
    k_mlp2<<<mg, 512, mlpSmem>>>(xmap, ymap, 1, 0, gy_b1, gy_b2, fx_b1, fx_b2,
                                 xrt, yrt, YD, XD, XD, YD);

    {
        dim3 rg((NROWS + 7) / 8, 4);
        k_red<<<rg, 256>>>(imap, x_w, y_w, out);
    }
    {
        dim3 qg((NQPAD * KP) / 256, 2);
        k_prep_q<<<qg, 256>>>(imap);
    }
    {
        dim3 ng(QTILES, GSPLIT, 2);
        k_nn<<<ng, 256, SMEM_NN>>>();
    }
    {
        dim3 eg((NQ + 7) / 8, 2);
        k_finish<<<eg, 256>>>(imap, 1.0f / NQ, out);
    }
}

// round 16
// speedup vs baseline: 2.4252x; 1.0173x over previous
#include <cuda_runtime.h>
#include <cuda_bf16.h>
#include <math.h>
#include <stdint.h>

// ---------------- problem constants ----------------
#define NROWS 25000
#define NQ    8000
#define XD    100
#define YD    120
#define HID   100
#define KP    128
#define NQPAD 8064          // 63*128
#define NTPAD 25088         // 196*128
#define QTILES 63
#define GSPLIT 14
#define NCH_PER 14
#define CSHIFT 8.0f
#define MP    132
#define WSTRIDE (128 * MP)

// ---------------- scratch ----------------
__device__ __align__(16) float g_xmap[NROWS * YD];
__device__ __align__(16) float g_ymap[NROWS * XD];
__device__ uint32_t g_Wt[4 * WSTRIDE];
__device__ __align__(16) __nv_bfloat16 g_QbA[NQPAD * KP];
__device__ __align__(16) __nv_bfloat16 g_QbB[NQPAD * KP];
__device__ __align__(16) __nv_bfloat16 g_TbA[NTPAD * KP];
__device__ __align__(16) __nv_bfloat16 g_TbB[NTPAD * KP];
__device__ unsigned int g_mbA[NQ];
__device__ unsigned int g_mbB[NQ];

// ---------------- helpers ----------------
__device__ __forceinline__ uint32_t smem_u32(const void* p) {
    uint32_t a;
    asm("{ .reg .u64 t; cvta.to.shared.u64 t, %1; cvt.u32.u64 %0, t; }" : "=r"(a) : "l"(p));
    return a;
}
__device__ __forceinline__ void cpa16(uint32_t dst, const void* src) {
    asm volatile("cp.async.cg.shared.global [%0], [%1], 16;" :: "r"(dst), "l"(src));
}
#define CP_COMMIT() asm volatile("cp.async.commit_group;" ::: "memory")
#define CP_WAIT0()  asm volatile("cp.async.wait_group 0;" ::: "memory")

__device__ __forceinline__ uint32_t f2tf32(float v) {
    uint32_t r;
    asm("cvt.rna.tf32.f32 %0, %1;" : "=r"(r) : "f"(v));
    return r;
}

// ---------------- init ----------------
__global__ void k_init(float* out) {
    int i = blockIdx.x * 256 + threadIdx.x;
    if (i == 0) out[0] = 0.0f;
    if (i < NQ) { g_mbA[i] = 0x7F800000u; g_mbB[i] = 0x7F800000u; }
}

// ---------------- weight prep (transposed, tf32 RNA, pitch MP) --------------
__global__ void k_wprep(const float* __restrict__ w0, const float* __restrict__ w1,
                        const float* __restrict__ w2, const float* __restrict__ w3)
{
    int idx = blockIdx.x * 256 + threadIdx.x;
    if (idx >= 4 * WSTRIDE) return;
    int m = idx / WSTRIDE, r = idx - m * WSTRIDE;
    int n = r / MP, k = r - n * MP;
    const float* src; int Kd, Nd;
    if (m == 0)      { src = w0; Kd = XD;  Nd = HID; }
    else if (m == 1) { src = w1; Kd = HID; Nd = YD;  }
    else if (m == 2) { src = w2; Kd = YD;  Nd = HID; }
    else             { src = w3; Kd = HID; Nd = XD;  }
    float v = (n < Nd && k < Kd) ? src[k * Nd + n] : 0.0f;
    g_Wt[idx] = f2tf32(v);
}

// ---------------- target prep (bf16 + folded tn, warp-cooperative) ----------
__global__ void k_prep_t(const float* __restrict__ x_w, const float* __restrict__ y_w)
{
    int z = blockIdx.y;
    const float* T = z ? x_w : y_w;
    int K = z ? XD : YD;
    __nv_bfloat16* Tb = z ? g_TbB : g_TbA;
    int tid = threadIdx.x, lane = tid & 31, wid = tid >> 5;
    int idx = blockIdx.x * 256 + tid;              // 2 rows per block
    int row = idx >> 7, col = idx & 127;
    bool rok = row < NROWS;
    float v = (rok && col < K) ? T[(size_t)row * K + col] : 0.0f;

    float s = v * v;
#pragma unroll
    for (int o = 16; o; o >>= 1) s += __shfl_xor_sync(0xffffffffu, s, o);
    __shared__ float sh[8];
    if (lane == 0) sh[wid] = s;
    __syncthreads();
    int rw = (tid >> 7) * 4;
    float tot = sh[rw] + sh[rw + 1] + sh[rw + 2] + sh[rw + 3] + CSHIFT;

    float o = v;
    if (col == K)          o = rok ? tot : 1.0e6f;
    else if (col == K + 1) o = rok ? (tot - __bfloat162float(__float2bfloat16(tot))) : 0.0f;
    Tb[idx] = __float2bfloat16(o);
}

// ---------------- fused 2-layer MLP; doNorm fuses cycle-norm epilogue --------
__global__ __launch_bounds__(512, 1)
void k_mlp2(const float* __restrict__ X0, const float* __restrict__ X1,
            int wsel0, int wsel1,
            const float* __restrict__ b1_0, const float* __restrict__ b2_0,
            const float* __restrict__ b1_1, const float* __restrict__ b2_1,
            float* __restrict__ Y0, float* __restrict__ Y1,
            const float* __restrict__ R0, const float* __restrict__ R1,
            float* __restrict__ out, int doNorm,
            int Kin0, int Nout0, int Kin1, int Nout1)
{
    extern __shared__ __align__(16) uint32_t sm[];
    uint32_t* Xs  = sm;
    uint32_t* W1t = Xs + 128 * MP;
    uint32_t* W2t = W1t + 128 * MP;
    __shared__ float sred[128];
    int tid = threadIdx.x, lane = tid & 31, wid = tid >> 5;
    int warp_m = wid >> 2, warp_n = wid & 3;
    int z = blockIdx.y;
    int m0 = blockIdx.x * 128;

    const float* X = z ? X1 : X0;
    int wsel = z ? wsel1 : wsel0;
    int Kin  = z ? Kin1 : Kin0;
    int Nout = z ? Nout1 : Nout0;
    const float* B1 = z ? b1_1 : b1_0;
    const float* B2 = z ? b2_1 : b2_0;
    float* Y = z ? Y1 : Y0;
    const float* R = z ? R1 : R0;

    for (int i = tid; i < 128 * 36; i += 512) {
        int r = i / 36, c = i - r * 36;
        Xs[r * MP + 96 + c] = 0;
    }
    if (doNorm) { if (tid < 128) sred[tid] = 0.0f; }
    __syncthreads();
    {
        uint32_t sX = smem_u32(Xs);
        int chunks = Kin >> 2;
        int tot = 128 * chunks;
        for (int i = tid; i < tot; i += 512) {
            int r = i / chunks, c = i - r * chunks;
            if (m0 + r < NROWS)
                cpa16(sX + r * (MP * 4) + c * 16, X + (size_t)(m0 + r) * Kin + c * 4);
        }
        uint32_t sW = smem_u32(W1t);
        const char* wsrc = (const char*)(g_Wt + (size_t)wsel * 2 * WSTRIDE);
        for (int i = tid; i < 8448; i += 512)
            cpa16(sW + i * 16, wsrc + i * 16);
        CP_COMMIT();
        CP_WAIT0();
    }
    __syncthreads();

    int r0 = lane >> 2, c0 = lane & 3;
    float acc[2][4][4];
    int nf1max = (warp_n < 3) ? 4 : 1;
    int nf2max = (warp_n < 3) ? 4 : ((Nout > 104) ? 3 : 1);

    // ---------------- stage 1 (A-fragments RNA-rounded from raw fp32) -------
#pragma unroll
    for (int mf = 0; mf < 2; mf++)
#pragma unroll
        for (int nf = 0; nf < 4; nf++)
#pragma unroll
            for (int r = 0; r < 4; r++) acc[mf][nf][r] = 0.0f;

    int ks1 = (Kin + 7) >> 3;
    for (int ks = 0; ks < ks1; ks++) {
        int kb = ks * 8;
        uint32_t a[2][4], b[4][2];
#pragma unroll
        for (int mf = 0; mf < 2; mf++) {
            int row = warp_m * 32 + mf * 16 + r0;
            const uint32_t* p = &Xs[row * MP + kb + c0];
            a[mf][0] = f2tf32(__uint_as_float(p[0]));
            a[mf][1] = f2tf32(__uint_as_float(p[8 * MP]));
            a[mf][2] = f2tf32(__uint_as_float(p[4]));
            a[mf][3] = f2tf32(__uint_as_float(p[8 * MP + 4]));
        }
#pragma unroll
        for (int nf = 0; nf < 4; nf++) {
            if (nf < nf1max) {
                int col = warp_n * 32 + nf * 8 + r0;
                const uint32_t* p = &W1t[col * MP + kb + c0];
                b[nf][0] = p[0]; b[nf][1] = p[4];
            }
        }
#pragma unroll
        for (int mf = 0; mf < 2; mf++)
#pragma unroll
            for (int nf = 0; nf < 4; nf++)
                if (nf < nf1max)
                    asm volatile(
                        "mma.sync.aligned.m16n8k8.row.col.f32.tf32.tf32.f32 "
                        "{%0,%1,%2,%3}, {%4,%5,%6,%7}, {%8,%9}, {%0,%1,%2,%3};"
                        : "+f"(acc[mf][nf][0]), "+f"(acc[mf][nf][1]),
                          "+f"(acc[mf][nf][2]), "+f"(acc[mf][nf][3])
                        : "r"(a[mf][0]), "r"(a[mf][1]), "r"(a[mf][2]), "r"(a[mf][3]),
                          "r"(b[nf][0]), "r"(b[nf][1]));
    }
    __syncthreads();

    // H = relu(acc + b1), RNA tf32, back into Xs (cols >= HID zeroed)
#pragma unroll
    for (int mf = 0; mf < 2; mf++)
#pragma unroll
        for (int nf = 0; nf < 4; nf++) {
            int row = warp_m * 32 + mf * 16 + r0;
            int col = warp_n * 32 + nf * 8 + c0 * 2;
            float bi0 = (col < HID) ? B1[col] : 0.0f;
            float bi1 = (col + 1 < HID) ? B1[col + 1] : 0.0f;
            float v0 = (col < HID) ? fmaxf(acc[mf][nf][0] + bi0, 0.0f) : 0.0f;
            float v1 = (col + 1 < HID) ? fmaxf(acc[mf][nf][1] + bi1, 0.0f) : 0.0f;
            float v2 = (col < HID) ? fmaxf(acc[mf][nf][2] + bi0, 0.0f) : 0.0f;
            float v3 = (col + 1 < HID) ? fmaxf(acc[mf][nf][3] + bi1, 0.0f) : 0.0f;
            Xs[row * MP + col]           = f2tf32(v0);
            Xs[row * MP + col + 1]       = f2tf32(v1);
            Xs[(row + 8) * MP + col]     = f2tf32(v2);
            Xs[(row + 8) * MP + col + 1] = f2tf32(v3);
        }
    __syncthreads();

    // ---------------- stage 2 (H already tf32) ----------------
#pragma unroll
    for (int mf = 0; mf < 2; mf++)
#pragma unroll
        for (int nf = 0; nf < 4; nf++)
#pragma unroll
            for (int r = 0; r < 4; r++) acc[mf][nf][r] = 0.0f;

    const int ks2 = (HID + 7) >> 3;
    for (int ks = 0; ks < ks2; ks++) {
        int kb = ks * 8;
        uint32_t a[2][4], b[4][2];
#pragma unroll
        for (int mf = 0; mf < 2; mf++) {
            int row = warp_m * 32 + mf * 16 + r0;
            const uint32_t* p = &Xs[row * MP + kb + c0];
            a[mf][0] = p[0]; a[mf][1] = p[8 * MP]; a[mf][2] = p[4]; a[mf][3] = p[8 * MP + 4];
        }
#pragma unroll
        for (int nf = 0; nf < 4; nf++) {
            if (nf < nf2max) {
                int col = warp_n * 32 + nf * 8 + r0;
                const uint32_t* p = &W2t[col * MP + kb + c0];
                b[nf][0] = p[0]; b[nf][1] = p[4];
            }
        }
#pragma unroll
        for (int mf = 0; mf < 2; mf++)
#pragma unroll
            for (int nf = 0; nf < 4; nf++)
                if (nf < nf2max)
                    asm volatile(
                        "mma.sync.aligned.m16n8k8.row.col.f32.tf32.tf32.f32 "
                        "{%0,%1,%2,%3}, {%4,%5,%6,%7}, {%8,%9}, {%0,%1,%2,%3};"
                        : "+f"(acc[mf][nf][0]), "+f"(acc[mf][nf][1]),
                          "+f"(acc[mf][nf][2]), "+f"(acc[mf][nf][3])
                        : "r"(a[mf][0]), "r"(a[mf][1]), "r"(a[mf][2]), "r"(a[mf][3]),
                          "r"(b[nf][0]), "r"(b[nf][1]));
    }

    if (!doNorm) {
        // epilogue: bias + store fp32
#pragma unroll
        for (int mf = 0; mf < 2; mf++)
#pragma unroll
            for (int nf = 0; nf < 4; nf++) {
                int row = warp_m * 32 + mf * 16 + r0;
                int col = warp_n * 32 + nf * 8 + c0 * 2;
                if (col < Nout) {
                    float bi0 = B2[col], bi1 = (col + 1 < Nout) ? B2[col + 1] : 0.0f;
                    if (m0 + row < NROWS)
                        *(float2*)&Y[(size_t)(m0 + row) * Nout + col] =
                            make_float2(acc[mf][nf][0] + bi0, acc[mf][nf][1] + bi1);
                    if (m0 + row + 8 < NROWS)
                        *(float2*)&Y[(size_t)(m0 + row + 8) * Nout + col] =
                            make_float2(acc[mf][nf][2] + bi0, acc[mf][nf][3] + bi1);
                }
            }
    } else {
        // epilogue: fused cycle-norm  mean_row ||y - R[row]||
        float part[2][2] = {{0.0f, 0.0f}, {0.0f, 0.0f}};
#pragma unroll
        for (int mf = 0; mf < 2; mf++)
#pragma unroll
            for (int nf = 0; nf < 4; nf++) {
                int row = warp_m * 32 + mf * 16 + r0;
                int col = warp_n * 32 + nf * 8 + c0 * 2;
                if (col < Nout) {
                    float bi0 = B2[col], bi1 = (col + 1 < Nout) ? B2[col + 1] : 0.0f;
                    if (m0 + row < NROWS) {
                        float2 rv = *(const float2*)&R[(size_t)(m0 + row) * Nout + col];
                        float d0 = acc[mf][nf][0] + bi0 - rv.x;
                        float d1 = acc[mf][nf][1] + bi1 - rv.y;
                        part[mf][0] += d0 * d0 + d1 * d1;
                    }
                    if (m0 + row + 8 < NROWS) {
                        float2 rv = *(const float2*)&R[(size_t)(m0 + row + 8) * Nout + col];
                        float d2 = acc[mf][nf][2] + bi0 - rv.x;
                        float d3 = acc[mf][nf][3] + bi1 - rv.y;
                        part[mf][1] += d2 * d2 + d3 * d3;
                    }
                }
            }
        // reduce over the 4 c0 lanes sharing each row
#pragma unroll
        for (int mf = 0; mf < 2; mf++)
#pragma unroll
            for (int s = 0; s < 2; s++) {
                float v = part[mf][s];
                v += __shfl_xor_sync(0xffffffffu, v, 1);
                v += __shfl_xor_sync(0xffffffffu, v, 2);
                part[mf][s] = v;
            }
        if ((lane & 3) == 0) {
            atomicAdd(&sred[warp_m * 32 + 0 * 16 + r0],     part[0][0]);
            atomicAdd(&sred[warp_m * 32 + 0 * 16 + r0 + 8], part[0][1]);
            atomicAdd(&sred[warp_m * 32 + 1 * 16 + r0],     part[1][0]);
            atomicAdd(&sred[warp_m * 32 + 1 * 16 + r0 + 8], part[1][1]);
        }
        __syncthreads();
        float rr = 0.0f;
        if (tid < 128 && m0 + tid < NROWS) rr = sqrtf(sred[tid]);
#pragma unroll
        for (int o = 16; o; o >>= 1) rr += __shfl_xor_sync(0xffffffffu, rr, o);
        __shared__ float sh2[16];
        if (lane == 0) sh2[wid] = rr;
        __syncthreads();
        if (tid == 0) {
            float t = 0.0f;
#pragma unroll
            for (int i = 0; i < 16; i++) t += sh2[i];
            if (t != 0.0f) atomicAdd(out, t * (1.0f / NROWS));
        }
    }
}

// ---------------- sup reductions only ----------------
__global__ void k_red(const int* __restrict__ imap,
                      const float* __restrict__ x_w, const float* __restrict__ y_w,
                      float* out)
{
    int z = blockIdx.y;
    int w = threadIdx.x >> 5, lane = threadIdx.x & 31;
    int idx = blockIdx.x * 8 + w;
    float r = 0.0f;
    if (idx < NQ) {
        const float* A = z ? g_ymap : g_xmap;
        const float* B = z ? x_w : y_w;
        int Kc = z ? XD : YD;
        const float* a = A + (size_t)imap[2 * idx + z] * Kc;
        const float* b = B + (size_t)imap[2 * idx + 1 - z] * Kc;
        float s = 0.0f;
        for (int j = lane; j < Kc; j += 32) { float d = a[j] - b[j]; s = fmaf(d, d, s); }
#pragma unroll
        for (int o = 16; o; o >>= 1) s += __shfl_xor_sync(0xffffffffu, s, o);
        r = sqrtf(s) * (1.0f / NQ);
    }
    __shared__ float sh[8];
    if (lane == 0) sh[w] = r;
    __syncthreads();
    if (threadIdx.x == 0) {
        float t = 0.0f;
#pragma unroll
        for (int i = 0; i < 8; i++) t += sh[i];
        if (t != 0.0f) atomicAdd(out, t);
    }
}

// ---------------- bf16 query prep ----------------
__global__ void k_prep_q(const int* __restrict__ imap)
{
    int z = blockIdx.y;
    const float* mapped = z ? g_ymap : g_xmap;
    int K = z ? XD : YD;
    __nv_bfloat16* Qb = z ? g_QbB : g_QbA;
    int idx = blockIdx.x * 256 + threadIdx.x;
    if (idx >= NQPAD * KP) return;
    int row = idx >> 7, col = idx & 127;
    float v = 0.0f;
    if (row < NQ) {
        if (col < K) v = -2.0f * mapped[(size_t)imap[2 * row + z] * K + col];
        else if (col <= K + 1) v = 1.0f;
    }
    Qb[idx] = __float2bfloat16(v);
}

// ---------------- mma.sync 1-NN proxy-min (128-query tiles) ------------------
#define PITCH_B 272
#define SM_B0   (128 * PITCH_B)
#define SM_B1   (SM_B0 + 128 * PITCH_B)
#define SM_MIN  (SM_B1 + 128 * PITCH_B)
#define SMEM_NN (SM_MIN + 512)

template <int NKS>
__device__ __forceinline__ void nn_side(const char* __restrict__ Qb,
                                        const char* __restrict__ Tb,
                                        unsigned* __restrict__ mb,
                                        char* dsm)
{
    constexpr int NC16 = NKS * 2;
    uint32_t sbase = smem_u32(dsm);
    unsigned* smin = (unsigned*)(dsm + SM_MIN);
    int tid = threadIdx.x, lane = tid & 31, wid = tid >> 5;
    int warp_m = wid >> 2, warp_n = wid & 3;
    int qtile = blockIdx.x, g = blockIdx.y;

    {
        const char* Ag = Qb + (size_t)qtile * 32768;
        const char* Bg = Tb + (size_t)(g * NCH_PER) * 32768;
        for (int i = tid; i < 2048; i += 256) {
            int row = i >> 4, c16 = i & 15;
            if (c16 < NC16) {
                cpa16(sbase + row * PITCH_B + c16 * 16, Ag + row * 256 + c16 * 16);
                cpa16(sbase + SM_B0 + row * PITCH_B + c16 * 16, Bg + row * 256 + c16 * 16);
            }
        }
        CP_COMMIT();
    }
    if (tid < 128) smin[tid] = 0x7F800000u;

    float best0[4], best1[4];
#pragma unroll
    for (int mf = 0; mf < 4; mf++) { best0[mf] = 1e30f; best1[mf] = 1e30f; }

    uint32_t aAddr = sbase + (uint32_t)((warp_m * 64 + (lane & 15)) * PITCH_B
                                        + ((lane >> 4) & 1) * 16);
    uint32_t bOff  = (uint32_t)((warp_n * 32 + (lane & 7)) * PITCH_B
                                + ((lane >> 3) & 1) * 16);

    for (int c = 0; c < NCH_PER; c++) {
        CP_WAIT0();
        __syncthreads();
        if (c + 1 < NCH_PER) {
            const char* Bg = Tb + (size_t)(g * NCH_PER + c + 1) * 32768;
            uint32_t dstb = sbase + (((c + 1) & 1) ? SM_B1 : SM_B0);
            for (int i = tid; i < 2048; i += 256) {
                int row = i >> 4, c16 = i & 15;
                if (c16 < NC16)
                    cpa16(dstb + row * PITCH_B + c16 * 16, Bg + row * 256 + c16 * 16);
            }
            CP_COMMIT();
        }
        uint32_t bAddr = sbase + ((c & 1) ? SM_B1 : SM_B0) + bOff;

        float acc[4][4][4];
#pragma unroll
        for (int mf = 0; mf < 4; mf++)
#pragma unroll
            for (int nf = 0; nf < 4; nf++)
#pragma unroll
                for (int r = 0; r < 4; r++) acc[mf][nf][r] = 0.0f;

#pragma unroll
        for (int ks = 0; ks < NKS; ks++) {
            uint32_t a[4][4], b[4][2];
#pragma unroll
            for (int mf = 0; mf < 4; mf++)
                asm volatile(
                    "ldmatrix.sync.aligned.m8n8.x4.shared.b16 {%0,%1,%2,%3}, [%4];"
                    : "=r"(a[mf][0]), "=r"(a[mf][1]), "=r"(a[mf][2]), "=r"(a[mf][3])
                    : "r"(aAddr + mf * 16 * PITCH_B + ks * 32));
#pragma unroll
            for (int nf = 0; nf < 4; nf++)
                asm volatile(
                    "ldmatrix.sync.aligned.m8n8.x2.shared.b16 {%0,%1}, [%2];"
                    : "=r"(b[nf][0]), "=r"(b[nf][1])
                    : "r"(bAddr + nf * 8 * PITCH_B + ks * 32));
#pragma unroll
            for (int mf = 0; mf < 4; mf++)
#pragma unroll
                for (int nf = 0; nf < 4; nf++)
                    asm volatile(
                        "mma.sync.aligned.m16n8k16.row.col.f32.bf16.bf16.f32 "
                        "{%0,%1,%2,%3}, {%4,%5,%6,%7}, {%8,%9}, {%0,%1,%2,%3};"
                        : "+f"(acc[mf][nf][0]), "+f"(acc[mf][nf][1]),
                          "+f"(acc[mf][nf][2]), "+f"(acc[mf][nf][3])
                        : "r"(a[mf][0]), "r"(a[mf][1]), "r"(a[mf][2]), "r"(a[mf][3]),
                          "r"(b[nf][0]), "r"(b[nf][1]));
        }
#pragma unroll
        for (int mf = 0; mf < 4; mf++)
#pragma unroll
            for (int nf = 0; nf < 4; nf++) {
                best0[mf] = fminf(best0[mf], fminf(acc[mf][nf][0], acc[mf][nf][1]));
                best1[mf] = fminf(best1[mf], fminf(acc[mf][nf][2], acc[mf][nf][3]));
            }
    }

#pragma unroll
    for (int mf = 0; mf < 4; mf++) {
        float v0 = best0[mf], v1 = best1[mf];
        v0 = fminf(v0, __shfl_xor_sync(0xffffffffu, v0, 1));
        v0 = fminf(v0, __shfl_xor_sync(0xffffffffu, v0, 2));
        v1 = fminf(v1, __shfl_xor_sync(0xffffffffu, v1, 1));
        v1 = fminf(v1, __shfl_xor_sync(0xffffffffu, v1, 2));
        if ((lane & 3) == 0) {
            int r = warp_m * 64 + mf * 16 + (lane >> 2);
            atomicMin(&smin[r], __float_as_uint(v0));
            atomicMin(&smin[r + 8], __float_as_uint(v1));
        }
    }
    __syncthreads();
    if (tid < 128) {
        int q = qtile * 128 + tid;
        if (q < NQ) atomicMin(&mb[q], smin[tid]);
    }
}

__global__ __launch_bounds__(256, 2)
void k_nn()
{
    extern __shared__ __align__(16) char dsm[];
    if (blockIdx.z == 0)
        nn_side<8>((const char*)g_QbA, (const char*)g_TbA, g_mbA, dsm);
    else
        nn_side<7>((const char*)g_QbB, (const char*)g_TbB, g_mbB, dsm);
}

// ---------------- finalize: inline pref dot + indicator ----------------
__global__ void k_finish(const int* __restrict__ imap, float scale, float* out)
{
    int z = blockIdx.y;
    const __nv_bfloat16* Qb = z ? g_QbB : g_QbA;
    const __nv_bfloat16* Tb = z ? g_TbB : g_TbA;
    const unsigned* mb = z ? g_mbB : g_mbA;
    int w = threadIdx.x >> 5, lane = threadIdx.x & 31;
    int q = blockIdx.x * 8 + w;
    float c = 0.0f;
    if (q < NQ) {
        int t = imap[2 * q + z];
        const __nv_bfloat16* qr = Qb + (size_t)q * KP;
        const __nv_bfloat16* tr = Tb + (size_t)t * KP;
        float s = 0.0f;
#pragma unroll
        for (int k = lane; k < KP; k += 32)
            s = fmaf(__bfloat162float(qr[k]), __bfloat162float(tr[k]), s);
#pragma unroll
        for (int o = 16; o; o >>= 1) s += __shfl_xor_sync(0xffffffffu, s, o);
        if (lane == 0) {
            float m = __uint_as_float(mb[q]);
            if (m < s - 1e-4f) c = 1.0f;
        }
    }
    __shared__ float sh[8];
    if (lane == 0) sh[w] = c;
    __syncthreads();
    if (threadIdx.x == 0) {
        float t = 0.0f;
#pragma unroll
        for (int i = 0; i < 8; i++) t += sh[i];
        if (t != 0.0f) atomicAdd(out, t * scale);
    }
}

// ---------------- host ----------------
extern "C" void kernel_launch(void* const* d_in, const int* in_sizes, int n_in,
                              void* d_out, int out_size)
{
    const float* x_w   = (const float*)d_in[0];
    const float* y_w   = (const float*)d_in[1];
    const float* fx_w1 = (const float*)d_in[2];
    const float* fx_b1 = (const float*)d_in[3];
    const float* fx_w2 = (const float*)d_in[4];
    const float* fx_b2 = (const float*)d_in[5];
    const float* gy_w1 = (const float*)d_in[6];
    const float* gy_b1 = (const float*)d_in[7];
    const float* gy_w2 = (const float*)d_in[8];
    const float* gy_b2 = (const float*)d_in[9];
    const int*   imap  = (const int*)d_in[10];
    float* out = (float*)d_out;

    float *xmap, *ymap;
    cudaGetSymbolAddress((void**)&xmap, g_xmap);
    cudaGetSymbolAddress((void**)&ymap, g_ymap);

    static int smemSet = 0;
    if (!smemSet) {
        cudaFuncSetAttribute(k_nn, cudaFuncAttributeMaxDynamicSharedMemorySize, SMEM_NN);
        cudaFuncSetAttribute(k_mlp2, cudaFuncAttributeMaxDynamicSharedMemorySize,
                             3 * 128 * MP * 4);
        smemSet = 1;
    }

    k_init<<<32, 256>>>(out);
    k_wprep<<<(4 * WSTRIDE + 255) / 256, 256>>>(fx_w1, fx_w2, gy_w1, gy_w2);
    {
        dim3 tg((NTPAD * KP) / 256, 2);
        k_prep_t<<<tg, 256>>>(x_w, y_w);
    }
    int mlpSmem = 3 * 128 * MP * 4;
    dim3 mg((NROWS + 127) / 128, 2);
    // launch1: z=0 fx(x_w)->xmap ; z=1 gy(y_w)->ymap
    k_mlp2<<<mg, 512, mlpSmem>>>(x_w, y_w, 0, 1, fx_b1, fx_b2, gy_b1, gy_b2,
                                 xmap, ymap, (const float*)0, (const float*)0,
                                 out, 0, XD, YD, YD, XD);
    // launch2 (fused cycle-norm): z=0 gy(xmap) vs x_w ; z=1 fx(ymap) vs y_w
    k_mlp2<<<mg, 512, mlpSmem>>>(xmap, ymap, 1, 0, gy_b1, gy_b2, fx_b1, fx_b2,
                                 (float*)0, (float*)0, x_w, y_w,
                                 out, 1, YD, XD, XD, YD);

    {
        dim3 rg((NQ + 7) / 8, 2);
        k_red<<<rg, 256>>>(imap, x_w, y_w, out);
    }
    {
        dim3 qg((NQPAD * KP) / 256, 2);
        k_prep_q<<<qg, 256>>>(imap);
    }
    {
        dim3 ng(QTILES, GSPLIT, 2);
        k_nn<<<ng, 256, SMEM_NN>>>();
    }
    {
        dim3 eg((NQ + 7) / 8, 2);
        k_finish<<<eg, 256>>>(imap, 1.0f / NQ, out);
    }
}

// round 17
// speedup vs baseline: 2.5286x; 1.0426x over previous
#include <cuda_runtime.h>
#include <cuda_bf16.h>
#include <math.h>
#include <stdint.h>

// ---------------- problem constants ----------------
#define NROWS 25000
#define NQ    8000
#define XD    100
#define YD    120
#define HID   100
#define KP    128
#define NQPAD 8064          // 63*128
#define NTPAD 25088         // 196*128
#define QTILES 63
#define GSPLIT 14
#define NCH_PER 14
#define CSHIFT 8.0f
#define MP    132
#define WFKS  16            // max k-steps in fragment layout
#define WFSTRIDE (WFKS * 128 * 4)   // uint2 entries per matrix

// ---------------- scratch ----------------
__device__ __align__(16) float g_xmap[NROWS * YD];
__device__ __align__(16) float g_ymap[NROWS * XD];
__device__ __align__(16) uint2 g_Wf[4 * WFSTRIDE];   // fragment-ordered tf32 weights
__device__ __align__(16) __nv_bfloat16 g_QbA[NQPAD * KP];
__device__ __align__(16) __nv_bfloat16 g_QbB[NQPAD * KP];
__device__ __align__(16) __nv_bfloat16 g_TbA[NTPAD * KP];
__device__ __align__(16) __nv_bfloat16 g_TbB[NTPAD * KP];
__device__ unsigned int g_mbA[NQ];
__device__ unsigned int g_mbB[NQ];

// ---------------- helpers ----------------
__device__ __forceinline__ uint32_t smem_u32(const void* p) {
    uint32_t a;
    asm("{ .reg .u64 t; cvta.to.shared.u64 t, %1; cvt.u32.u64 %0, t; }" : "=r"(a) : "l"(p));
    return a;
}
__device__ __forceinline__ void cpa16(uint32_t dst, const void* src) {
    asm volatile("cp.async.cg.shared.global [%0], [%1], 16;" :: "r"(dst), "l"(src));
}
#define CP_COMMIT() asm volatile("cp.async.commit_group;" ::: "memory")
#define CP_WAIT0()  asm volatile("cp.async.wait_group 0;" ::: "memory")

__device__ __forceinline__ uint32_t f2tf32(float v) {
    uint32_t r;
    asm("cvt.rna.tf32.f32 %0, %1;" : "=r"(r) : "f"(v));
    return r;
}

// ---------------- init ----------------
__global__ void k_init(float* out) {
    int i = blockIdx.x * 256 + threadIdx.x;
    if (i == 0) out[0] = 0.0f;
    if (i < NQ) { g_mbA[i] = 0x7F800000u; g_mbB[i] = 0x7F800000u; }
}

// ---------------- weight prep: fragment-ordered tf32 ------------------------
// Wf[m][ks][col][c0] = { tf32(W[ks*8+c0][col]), tf32(W[ks*8+c0+4][col]) }
__global__ void k_wprep(const float* __restrict__ w0, const float* __restrict__ w1,
                        const float* __restrict__ w2, const float* __restrict__ w3)
{
    int idx = blockIdx.x * 256 + threadIdx.x;
    if (idx >= 4 * WFSTRIDE) return;
    int m = idx / WFSTRIDE, r = idx - m * WFSTRIDE;
    int ks = r >> 9;
    int col = (r >> 2) & 127;
    int c0 = r & 3;
    const float* src; int Kd, Nd;
    if (m == 0)      { src = w0; Kd = XD;  Nd = HID; }
    else if (m == 1) { src = w1; Kd = HID; Nd = YD;  }
    else if (m == 2) { src = w2; Kd = YD;  Nd = HID; }
    else             { src = w3; Kd = HID; Nd = XD;  }
    int k0 = ks * 8 + c0, k1 = k0 + 4;
    float v0 = (col < Nd && k0 < Kd) ? src[k0 * Nd + col] : 0.0f;
    float v1 = (col < Nd && k1 < Kd) ? src[k1 * Nd + col] : 0.0f;
    g_Wf[idx] = make_uint2(f2tf32(v0), f2tf32(v1));
}

// ---------------- target prep (bf16 + folded tn, warp-cooperative) ----------
__global__ void k_prep_t(const float* __restrict__ x_w, const float* __restrict__ y_w)
{
    int z = blockIdx.y;
    const float* T = z ? x_w : y_w;
    int K = z ? XD : YD;
    __nv_bfloat16* Tb = z ? g_TbB : g_TbA;
    int tid = threadIdx.x, lane = tid & 31, wid = tid >> 5;
    int idx = blockIdx.x * 256 + tid;
    int row = idx >> 7, col = idx & 127;
    bool rok = row < NROWS;
    float v = (rok && col < K) ? T[(size_t)row * K + col] : 0.0f;

    float s = v * v;
#pragma unroll
    for (int o = 16; o; o >>= 1) s += __shfl_xor_sync(0xffffffffu, s, o);
    __shared__ float sh[8];
    if (lane == 0) sh[wid] = s;
    __syncthreads();
    int rw = (tid >> 7) * 4;
    float tot = sh[rw] + sh[rw + 1] + sh[rw + 2] + sh[rw + 3] + CSHIFT;

    float o = v;
    if (col == K)          o = rok ? tot : 1.0e6f;
    else if (col == K + 1) o = rok ? (tot - __bfloat162float(__float2bfloat16(tot))) : 0.0f;
    Tb[idx] = __float2bfloat16(o);
}

// ---------------- fused 2-layer MLP; weights via coalesced LDG fragments -----
__global__ __launch_bounds__(512, 2)
void k_mlp2(const float* __restrict__ X0, const float* __restrict__ X1,
            int wsel0, int wsel1,
            const float* __restrict__ b1_0, const float* __restrict__ b2_0,
            const float* __restrict__ b1_1, const float* __restrict__ b2_1,
            float* __restrict__ Y0, float* __restrict__ Y1,
            const float* __restrict__ R0, const float* __restrict__ R1,
            float* __restrict__ out, int doNorm,
            int Kin0, int Nout0, int Kin1, int Nout1)
{
    extern __shared__ __align__(16) uint32_t Xs[];   // [128][MP]
    __shared__ float sred[128];
    int tid = threadIdx.x, lane = tid & 31, wid = tid >> 5;
    int warp_m = wid >> 2, warp_n = wid & 3;
    int z = blockIdx.y;
    int m0 = blockIdx.x * 128;

    const float* X = z ? X1 : X0;
    int wsel = z ? wsel1 : wsel0;
    int Kin  = z ? Kin1 : Kin0;
    int Nout = z ? Nout1 : Nout0;
    const float* B1 = z ? b1_1 : b1_0;
    const float* B2 = z ? b2_1 : b2_0;
    float* Y = z ? Y1 : Y0;
    const float* R = z ? R1 : R0;
    const uint2* Wf1 = g_Wf + (size_t)(wsel * 2) * WFSTRIDE;
    const uint2* Wf2 = Wf1 + WFSTRIDE;

    for (int i = tid; i < 128 * 36; i += 512) {
        int r = i / 36, c = i - r * 36;
        Xs[r * MP + 96 + c] = 0;
    }
    if (doNorm) { if (tid < 128) sred[tid] = 0.0f; }
    __syncthreads();
    {
        uint32_t sX = smem_u32(Xs);
        int chunks = Kin >> 2;
        int tot = 128 * chunks;
        for (int i = tid; i < tot; i += 512) {
            int r = i / chunks, c = i - r * chunks;
            if (m0 + r < NROWS)
                cpa16(sX + r * (MP * 4) + c * 16, X + (size_t)(m0 + r) * Kin + c * 4);
        }
        CP_COMMIT();
        CP_WAIT0();
    }
    __syncthreads();

    int r0 = lane >> 2, c0 = lane & 3;
    float acc[2][4][4];
    int nf1max = (warp_n < 3) ? 4 : 1;
    int nf2max = (warp_n < 3) ? 4 : ((Nout > 104) ? 3 : 1);

    // ---------------- stage 1 (A RNA-rounded; B via LDG fragments) ----------
#pragma unroll
    for (int mf = 0; mf < 2; mf++)
#pragma unroll
        for (int nf = 0; nf < 4; nf++)
#pragma unroll
            for (int r = 0; r < 4; r++) acc[mf][nf][r] = 0.0f;

    int ks1 = (Kin + 7) >> 3;
    for (int ks = 0; ks < ks1; ks++) {
        int kb = ks * 8;
        uint32_t a[2][4], b[4][2];
#pragma unroll
        for (int mf = 0; mf < 2; mf++) {
            int row = warp_m * 32 + mf * 16 + r0;
            const uint32_t* p = &Xs[row * MP + kb + c0];
            a[mf][0] = f2tf32(__uint_as_float(p[0]));
            a[mf][1] = f2tf32(__uint_as_float(p[8 * MP]));
            a[mf][2] = f2tf32(__uint_as_float(p[4]));
            a[mf][3] = f2tf32(__uint_as_float(p[8 * MP + 4]));
        }
#pragma unroll
        for (int nf = 0; nf < 4; nf++) {
            if (nf < nf1max) {
                int col = warp_n * 32 + nf * 8 + r0;
                uint2 w = __ldg(&Wf1[(ks * 128 + col) * 4 + c0]);
                b[nf][0] = w.x; b[nf][1] = w.y;
            }
        }
#pragma unroll
        for (int mf = 0; mf < 2; mf++)
#pragma unroll
            for (int nf = 0; nf < 4; nf++)
                if (nf < nf1max)
                    asm volatile(
                        "mma.sync.aligned.m16n8k8.row.col.f32.tf32.tf32.f32 "
                        "{%0,%1,%2,%3}, {%4,%5,%6,%7}, {%8,%9}, {%0,%1,%2,%3};"
                        : "+f"(acc[mf][nf][0]), "+f"(acc[mf][nf][1]),
                          "+f"(acc[mf][nf][2]), "+f"(acc[mf][nf][3])
                        : "r"(a[mf][0]), "r"(a[mf][1]), "r"(a[mf][2]), "r"(a[mf][3]),
                          "r"(b[nf][0]), "r"(b[nf][1]));
    }
    __syncthreads();

    // H = relu(acc + b1), RNA tf32, back into Xs (cols >= HID zeroed)
#pragma unroll
    for (int mf = 0; mf < 2; mf++)
#pragma unroll
        for (int nf = 0; nf < 4; nf++) {
            int row = warp_m * 32 + mf * 16 + r0;
            int col = warp_n * 32 + nf * 8 + c0 * 2;
            float bi0 = (col < HID) ? B1[col] : 0.0f;
            float bi1 = (col + 1 < HID) ? B1[col + 1] : 0.0f;
            float v0 = (col < HID) ? fmaxf(acc[mf][nf][0] + bi0, 0.0f) : 0.0f;
            float v1 = (col + 1 < HID) ? fmaxf(acc[mf][nf][1] + bi1, 0.0f) : 0.0f;
            float v2 = (col < HID) ? fmaxf(acc[mf][nf][2] + bi0, 0.0f) : 0.0f;
            float v3 = (col + 1 < HID) ? fmaxf(acc[mf][nf][3] + bi1, 0.0f) : 0.0f;
            Xs[row * MP + col]           = f2tf32(v0);
            Xs[row * MP + col + 1]       = f2tf32(v1);
            Xs[(row + 8) * MP + col]     = f2tf32(v2);
            Xs[(row + 8) * MP + col + 1] = f2tf32(v3);
        }
    __syncthreads();

    // ---------------- stage 2 (H already tf32) ----------------
#pragma unroll
    for (int mf = 0; mf < 2; mf++)
#pragma unroll
        for (int nf = 0; nf < 4; nf++)
#pragma unroll
            for (int r = 0; r < 4; r++) acc[mf][nf][r] = 0.0f;

    const int ks2 = (HID + 7) >> 3;
    for (int ks = 0; ks < ks2; ks++) {
        int kb = ks * 8;
        uint32_t a[2][4], b[4][2];
#pragma unroll
        for (int mf = 0; mf < 2; mf++) {
            int row = warp_m * 32 + mf * 16 + r0;
            const uint32_t* p = &Xs[row * MP + kb + c0];
            a[mf][0] = p[0]; a[mf][1] = p[8 * MP]; a[mf][2] = p[4]; a[mf][3] = p[8 * MP + 4];
        }
#pragma unroll
        for (int nf = 0; nf < 4; nf++) {
            if (nf < nf2max) {
                int col = warp_n * 32 + nf * 8 + r0;
                uint2 w = __ldg(&Wf2[(ks * 128 + col) * 4 + c0]);
                b[nf][0] = w.x; b[nf][1] = w.y;
            }
        }
#pragma unroll
        for (int mf = 0; mf < 2; mf++)
#pragma unroll
            for (int nf = 0; nf < 4; nf++)
                if (nf < nf2max)
                    asm volatile(
                        "mma.sync.aligned.m16n8k8.row.col.f32.tf32.tf32.f32 "
                        "{%0,%1,%2,%3}, {%4,%5,%6,%7}, {%8,%9}, {%0,%1,%2,%3};"
                        : "+f"(acc[mf][nf][0]), "+f"(acc[mf][nf][1]),
                          "+f"(acc[mf][nf][2]), "+f"(acc[mf][nf][3])
                        : "r"(a[mf][0]), "r"(a[mf][1]), "r"(a[mf][2]), "r"(a[mf][3]),
                          "r"(b[nf][0]), "r"(b[nf][1]));
    }

    if (!doNorm) {
#pragma unroll
        for (int mf = 0; mf < 2; mf++)
#pragma unroll
            for (int nf = 0; nf < 4; nf++) {
                int row = warp_m * 32 + mf * 16 + r0;
                int col = warp_n * 32 + nf * 8 + c0 * 2;
                if (col < Nout) {
                    float bi0 = B2[col], bi1 = (col + 1 < Nout) ? B2[col + 1] : 0.0f;
                    if (m0 + row < NROWS)
                        *(float2*)&Y[(size_t)(m0 + row) * Nout + col] =
                            make_float2(acc[mf][nf][0] + bi0, acc[mf][nf][1] + bi1);
                    if (m0 + row + 8 < NROWS)
                        *(float2*)&Y[(size_t)(m0 + row + 8) * Nout + col] =
                            make_float2(acc[mf][nf][2] + bi0, acc[mf][nf][3] + bi1);
                }
            }
    } else {
        // fused cycle-norm  mean_row ||y - R[row]||
        float part[2][2] = {{0.0f, 0.0f}, {0.0f, 0.0f}};
#pragma unroll
        for (int mf = 0; mf < 2; mf++)
#pragma unroll
            for (int nf = 0; nf < 4; nf++) {
                int row = warp_m * 32 + mf * 16 + r0;
                int col = warp_n * 32 + nf * 8 + c0 * 2;
                if (col < Nout) {
                    float bi0 = B2[col], bi1 = (col + 1 < Nout) ? B2[col + 1] : 0.0f;
                    if (m0 + row < NROWS) {
                        float2 rv = *(const float2*)&R[(size_t)(m0 + row) * Nout + col];
                        float d0 = acc[mf][nf][0] + bi0 - rv.x;
                        float d1 = acc[mf][nf][1] + bi1 - rv.y;
                        part[mf][0] += d0 * d0 + d1 * d1;
                    }
                    if (m0 + row + 8 < NROWS) {
                        float2 rv = *(const float2*)&R[(size_t)(m0 + row + 8) * Nout + col];
                        float d2 = acc[mf][nf][2] + bi0 - rv.x;
                        float d3 = acc[mf][nf][3] + bi1 - rv.y;
                        part[mf][1] += d2 * d2 + d3 * d3;
                    }
                }
            }
#pragma unroll
        for (int mf = 0; mf < 2; mf++)
#pragma unroll
            for (int s = 0; s < 2; s++) {
                float v = part[mf][s];
                v += __shfl_xor_sync(0xffffffffu, v, 1);
                v += __shfl_xor_sync(0xffffffffu, v, 2);
                part[mf][s] = v;
            }
        if ((lane & 3) == 0) {
            atomicAdd(&sred[warp_m * 32 + 0 * 16 + r0],     part[0][0]);
            atomicAdd(&sred[warp_m * 32 + 0 * 16 + r0 + 8], part[0][1]);
            atomicAdd(&sred[warp_m * 32 + 1 * 16 + r0],     part[1][0]);
            atomicAdd(&sred[warp_m * 32 + 1 * 16 + r0 + 8], part[1][1]);
        }
        __syncthreads();
        float rr = 0.0f;
        if (tid < 128 && m0 + tid < NROWS) rr = sqrtf(sred[tid]);
#pragma unroll
        for (int o = 16; o; o >>= 1) rr += __shfl_xor_sync(0xffffffffu, rr, o);
        __shared__ float sh2[16];
        if (lane == 0) sh2[wid] = rr;
        __syncthreads();
        if (tid == 0) {
            float t = 0.0f;
#pragma unroll
            for (int i = 0; i < 16; i++) t += sh2[i];
            if (t != 0.0f) atomicAdd(out, t * (1.0f / NROWS));
        }
    }
}

// ---------------- sup reductions only ----------------
__global__ void k_red(const int* __restrict__ imap,
                      const float* __restrict__ x_w, const float* __restrict__ y_w,
                      float* out)
{
    int z = blockIdx.y;
    int w = threadIdx.x >> 5, lane = threadIdx.x & 31;
    int idx = blockIdx.x * 8 + w;
    float r = 0.0f;
    if (idx < NQ) {
        const float* A = z ? g_ymap : g_xmap;
        const float* B = z ? x_w : y_w;
        int Kc = z ? XD : YD;
        const float* a = A + (size_t)imap[2 * idx + z] * Kc;
        const float* b = B + (size_t)imap[2 * idx + 1 - z] * Kc;
        float s = 0.0f;
        for (int j = lane; j < Kc; j += 32) { float d = a[j] - b[j]; s = fmaf(d, d, s); }
#pragma unroll
        for (int o = 16; o; o >>= 1) s += __shfl_xor_sync(0xffffffffu, s, o);
        r = sqrtf(s) * (1.0f / NQ);
    }
    __shared__ float sh[8];
    if (lane == 0) sh[w] = r;
    __syncthreads();
    if (threadIdx.x == 0) {
        float t = 0.0f;
#pragma unroll
        for (int i = 0; i < 8; i++) t += sh[i];
        if (t != 0.0f) atomicAdd(out, t);
    }
}

// ---------------- bf16 query prep ----------------
__global__ void k_prep_q(const int* __restrict__ imap)
{
    int z = blockIdx.y;
    const float* mapped = z ? g_ymap : g_xmap;
    int K = z ? XD : YD;
    __nv_bfloat16* Qb = z ? g_QbB : g_QbA;
    int idx = blockIdx.x * 256 + threadIdx.x;
    if (idx >= NQPAD * KP) return;
    int row = idx >> 7, col = idx & 127;
    float v = 0.0f;
    if (row < NQ) {
        if (col < K) v = -2.0f * mapped[(size_t)imap[2 * row + z] * K + col];
        else if (col <= K + 1) v = 1.0f;
    }
    Qb[idx] = __float2bfloat16(v);
}

// ---------------- mma.sync 1-NN proxy-min (128-query tiles) ------------------
#define PITCH_B 272
#define SM_B0   (128 * PITCH_B)
#define SM_B1   (SM_B0 + 128 * PITCH_B)
#define SM_MIN  (SM_B1 + 128 * PITCH_B)
#define SMEM_NN (SM_MIN + 512)

template <int NKS>
__device__ __forceinline__ void nn_side(const char* __restrict__ Qb,
                                        const char* __restrict__ Tb,
                                        unsigned* __restrict__ mb,
                                        char* dsm)
{
    constexpr int NC16 = NKS * 2;
    uint32_t sbase = smem_u32(dsm);
    unsigned* smin = (unsigned*)(dsm + SM_MIN);
    int tid = threadIdx.x, lane = tid & 31, wid = tid >> 5;
    int warp_m = wid >> 2, warp_n = wid & 3;
    int qtile = blockIdx.x, g = blockIdx.y;

    {
        const char* Ag = Qb + (size_t)qtile * 32768;
        const char* Bg = Tb + (size_t)(g * NCH_PER) * 32768;
        for (int i = tid; i < 2048; i += 256) {
            int row = i >> 4, c16 = i & 15;
            if (c16 < NC16) {
                cpa16(sbase + row * PITCH_B + c16 * 16, Ag + row * 256 + c16 * 16);
                cpa16(sbase + SM_B0 + row * PITCH_B + c16 * 16, Bg + row * 256 + c16 * 16);
            }
        }
        CP_COMMIT();
    }
    if (tid < 128) smin[tid] = 0x7F800000u;

    float best0[4], best1[4];
#pragma unroll
    for (int mf = 0; mf < 4; mf++) { best0[mf] = 1e30f; best1[mf] = 1e30f; }

    uint32_t aAddr = sbase + (uint32_t)((warp_m * 64 + (lane & 15)) * PITCH_B
                                        + ((lane >> 4) & 1) * 16);
    uint32_t bOff  = (uint32_t)((warp_n * 32 + (lane & 7)) * PITCH_B
                                + ((lane >> 3) & 1) * 16);

    for (int c = 0; c < NCH_PER; c++) {
        CP_WAIT0();
        __syncthreads();
        if (c + 1 < NCH_PER) {
            const char* Bg = Tb + (size_t)(g * NCH_PER + c + 1) * 32768;
            uint32_t dstb = sbase + (((c + 1) & 1) ? SM_B1 : SM_B0);
            for (int i = tid; i < 2048; i += 256) {
                int row = i >> 4, c16 = i & 15;
                if (c16 < NC16)
                    cpa16(dstb + row * PITCH_B + c16 * 16, Bg + row * 256 + c16 * 16);
            }
            CP_COMMIT();
        }
        uint32_t bAddr = sbase + ((c & 1) ? SM_B1 : SM_B0) + bOff;

        float acc[4][4][4];
#pragma unroll
        for (int mf = 0; mf < 4; mf++)
#pragma unroll
            for (int nf = 0; nf < 4; nf++)
#pragma unroll
                for (int r = 0; r < 4; r++) acc[mf][nf][r] = 0.0f;

#pragma unroll
        for (int ks = 0; ks < NKS; ks++) {
            uint32_t a[4][4], b[4][2];
#pragma unroll
            for (int mf = 0; mf < 4; mf++)
                asm volatile(
                    "ldmatrix.sync.aligned.m8n8.x4.shared.b16 {%0,%1,%2,%3}, [%4];"
                    : "=r"(a[mf][0]), "=r"(a[mf][1]), "=r"(a[mf][2]), "=r"(a[mf][3])
                    : "r"(aAddr + mf * 16 * PITCH_B + ks * 32));
#pragma unroll
            for (int nf = 0; nf < 4; nf++)
                asm volatile(
                    "ldmatrix.sync.aligned.m8n8.x2.shared.b16 {%0,%1}, [%2];"
                    : "=r"(b[nf][0]), "=r"(b[nf][1])
                    : "r"(bAddr + nf * 8 * PITCH_B + ks * 32));
#pragma unroll
            for (int mf = 0; mf < 4; mf++)
#pragma unroll
                for (int nf = 0; nf < 4; nf++)
                    asm volatile(
                        "mma.sync.aligned.m16n8k16.row.col.f32.bf16.bf16.f32 "
                        "{%0,%1,%2,%3}, {%4,%5,%6,%7}, {%8,%9}, {%0,%1,%2,%3};"
                        : "+f"(acc[mf][nf][0]), "+f"(acc[mf][nf][1]),
                          "+f"(acc[mf][nf][2]), "+f"(acc[mf][nf][3])
                        : "r"(a[mf][0]), "r"(a[mf][1]), "r"(a[mf][2]), "r"(a[mf][3]),
                          "r"(b[nf][0]), "r"(b[nf][1]));
        }
#pragma unroll
        for (int mf = 0; mf < 4; mf++)
#pragma unroll
            for (int nf = 0; nf < 4; nf++) {
                best0[mf] = fminf(best0[mf], fminf(acc[mf][nf][0], acc[mf][nf][1]));
                best1[mf] = fminf(best1[mf], fminf(acc[mf][nf][2], acc[mf][nf][3]));
            }
    }

#pragma unroll
    for (int mf = 0; mf < 4; mf++) {
        float v0 = best0[mf], v1 = best1[mf];
        v0 = fminf(v0, __shfl_xor_sync(0xffffffffu, v0, 1));
        v0 = fminf(v0, __shfl_xor_sync(0xffffffffu, v0, 2));
        v1 = fminf(v1, __shfl_xor_sync(0xffffffffu, v1, 1));
        v1 = fminf(v1, __shfl_xor_sync(0xffffffffu, v1, 2));
        if ((lane & 3) == 0) {
            int r = warp_m * 64 + mf * 16 + (lane >> 2);
            atomicMin(&smin[r], __float_as_uint(v0));
            atomicMin(&smin[r + 8], __float_as_uint(v1));
        }
    }
    __syncthreads();
    if (tid < 128) {
        int q = qtile * 128 + tid;
        if (q < NQ) atomicMin(&mb[q], smin[tid]);
    }
}

__global__ __launch_bounds__(256, 2)
void k_nn()
{
    extern __shared__ __align__(16) char dsm[];
    if (blockIdx.z == 0)
        nn_side<8>((const char*)g_QbA, (const char*)g_TbA, g_mbA, dsm);
    else
        nn_side<7>((const char*)g_QbB, (const char*)g_TbB, g_mbB, dsm);
}

// ---------------- finalize: inline pref dot + indicator ----------------
__global__ void k_finish(const int* __restrict__ imap, float scale, float* out)
{
    int z = blockIdx.y;
    const __nv_bfloat16* Qb = z ? g_QbB : g_QbA;
    const __nv_bfloat16* Tb = z ? g_TbB : g_TbA;
    const unsigned* mb = z ? g_mbB : g_mbA;
    int w = threadIdx.x >> 5, lane = threadIdx.x & 31;
    int q = blockIdx.x * 8 + w;
    float c = 0.0f;
    if (q < NQ) {
        int t = imap[2 * q + z];
        const __nv_bfloat16* qr = Qb + (size_t)q * KP;
        const __nv_bfloat16* tr = Tb + (size_t)t * KP;
        float s = 0.0f;
#pragma unroll
        for (int k = lane; k < KP; k += 32)
            s = fmaf(__bfloat162float(qr[k]), __bfloat162float(tr[k]), s);
#pragma unroll
        for (int o = 16; o; o >>= 1) s += __shfl_xor_sync(0xffffffffu, s, o);
        if (lane == 0) {
            float m = __uint_as_float(mb[q]);
            if (m < s - 1e-4f) c = 1.0f;
        }
    }
    __shared__ float sh[8];
    if (lane == 0) sh[w] = c;
    __syncthreads();
    if (threadIdx.x == 0) {
        float t = 0.0f;
#pragma unroll
        for (int i = 0; i < 8; i++) t += sh[i];
        if (t != 0.0f) atomicAdd(out, t * scale);
    }
}

// ---------------- host ----------------
extern "C" void kernel_launch(void* const* d_in, const int* in_sizes, int n_in,
                              void* d_out, int out_size)
{
    const float* x_w   = (const float*)d_in[0];
    const float* y_w   = (const float*)d_in[1];
    const float* fx_w1 = (const float*)d_in[2];
    const float* fx_b1 = (const float*)d_in[3];
    const float* fx_w2 = (const float*)d_in[4];
    const float* fx_b2 = (const float*)d_in[5];
    const float* gy_w1 = (const float*)d_in[6];
    const float* gy_b1 = (const float*)d_in[7];
    const float* gy_w2 = (const float*)d_in[8];
    const float* gy_b2 = (const float*)d_in[9];
    const int*   imap  = (const int*)d_in[10];
    float* out = (float*)d_out;

    float *xmap, *ymap;
    cudaGetSymbolAddress((void**)&xmap, g_xmap);
    cudaGetSymbolAddress((void**)&ymap, g_ymap);

    static int smemSet = 0;
    if (!smemSet) {
        cudaFuncSetAttribute(k_nn, cudaFuncAttributeMaxDynamicSharedMemorySize, SMEM_NN);
        cudaFuncSetAttribute(k_mlp2, cudaFuncAttributeMaxDynamicSharedMemorySize,
                             128 * MP * 4);
        smemSet = 1;
    }

    k_init<<<32, 256>>>(out);
    k_wprep<<<(4 * WFSTRIDE + 255) / 256, 256>>>(fx_w1, fx_w2, gy_w1, gy_w2);
    {
        dim3 tg((NTPAD * KP) / 256, 2);
        k_prep_t<<<tg, 256>>>(x_w, y_w);
    }
    int mlpSmem = 128 * MP * 4;
    dim3 mg((NROWS + 127) / 128, 2);
    // launch1: z=0 fx(x_w)->xmap ; z=1 gy(y_w)->ymap
    k_mlp2<<<mg, 512, mlpSmem>>>(x_w, y_w, 0, 1, fx_b1, fx_b2, gy_b1, gy_b2,
                                 xmap, ymap, (const float*)0, (const float*)0,
                                 out, 0, XD, YD, YD, XD);
    // launch2 (fused cycle-norm): z=0 gy(xmap) vs x_w ; z=1 fx(ymap) vs y_w
    k_mlp2<<<mg, 512, mlpSmem>>>(xmap, ymap, 1, 0, gy_b1, gy_b2, fx_b1, fx_b2,
                                 (float*)0, (float*)0, x_w, y_w,
                                 out, 1, YD, XD, XD, YD);

    {
        dim3 rg((NQ + 7) / 8, 2);
        k_red<<<rg, 256>>>(imap, x_w, y_w, out);
    }
    {
        dim3 qg((NQPAD * KP) / 256, 2);
        k_prep_q<<<qg, 256>>>(imap);
    }
    {
        dim3 ng(QTILES, GSPLIT, 2);
        k_nn<<<ng, 256, SMEM_NN>>>();
    }
    {
        dim3 eg((NQ + 7) / 8, 2);
        k_finish<<<eg, 256>>>(imap, 1.0f / NQ, out);
    }
}